// round 5
// baseline (speedup 1.0000x reference)
#include <cuda_runtime.h>
#include <cuda_fp16.h>
#include <cstddef>
#include <cstdint>

#define Bn   4
#define Nn   8192
#define Cn   512
#define DHn  128
#define QK_SPLIT 16

// ---------------- scratch (device globals) ---------------------------------
__device__ __align__(128) __half g_xh  [(size_t)Bn * Nn * Cn];
__device__ __align__(128) __half g_wqh [1536 * 512];
__device__ __align__(128) __half g_woh [512 * 512];
__device__ __align__(128) __half g_qkv [(size_t)Bn * 1536 * Nn];   // channel-major
__device__ __align__(128) __half g_vt  [(size_t)Bn * Nn * Cn];     // v token-major
__device__ __align__(128) float  g_inv [Bn * 1024];
__device__ __align__(128) float  g_attnP[16 * QK_SPLIT * DHn * DHn];
__device__ __align__(128) __half g_attn [16 * DHn * DHn];
__device__ __align__(128) __half g_xca [(size_t)Bn * Nn * Cn];

// ---------------- PTX helpers ----------------------------------------------
__device__ __forceinline__ uint32_t sptr(const void* p) {
    return (uint32_t)__cvta_generic_to_shared(p);
}
#define CPA(dst, src) asm volatile("cp.async.ca.shared.global [%0],[%1],16;\n" \
                                   :: "r"(dst), "l"(src))
#define CPC() asm volatile("cp.async.commit_group;\n")
#define CPW0() asm volatile("cp.async.wait_group 0;\n")
#define CPW1() asm volatile("cp.async.wait_group 1;\n")

__device__ __forceinline__ void ldmx4(uint32_t* r, uint32_t a) {
    asm volatile("ldmatrix.sync.aligned.m8n8.x4.shared.b16 {%0,%1,%2,%3},[%4];"
                 : "=r"(r[0]), "=r"(r[1]), "=r"(r[2]), "=r"(r[3]) : "r"(a));
}
__device__ __forceinline__ void ldmx2(uint32_t* r, uint32_t a) {
    asm volatile("ldmatrix.sync.aligned.m8n8.x2.shared.b16 {%0,%1},[%2];"
                 : "=r"(r[0]), "=r"(r[1]) : "r"(a));
}
__device__ __forceinline__ void mma16816(float* c, const uint32_t* a, const uint32_t* b) {
    asm volatile(
        "mma.sync.aligned.m16n8k16.row.col.f32.f16.f16.f32 "
        "{%0,%1,%2,%3},{%4,%5,%6,%7},{%8,%9},{%0,%1,%2,%3};"
        : "+f"(c[0]), "+f"(c[1]), "+f"(c[2]), "+f"(c[3])
        : "r"(a[0]), "r"(a[1]), "r"(a[2]), "r"(a[3]), "r"(b[0]), "r"(b[1]));
}

// ---------------------------------------------------------------------------
// BIG TILE fp16 A@B^T GEMM: CTA 128(m) x 256(n), 8 warps with 64x64 warp
// tiles, BK=32, cp.async double buffered, dynamic smem.
// A[m,:K], B[n,:K] both K-contiguous fp16, fp32 accumulate.
// ---------------------------------------------------------------------------
#define BIG_SMEM (2 * (128 * 40 + 256 * 40) * 2)   // 61440 bytes

template<bool HALF_OUT, bool BIAS>
__device__ __forceinline__ void gemm_big(
    const __half* __restrict__ A, const __half* __restrict__ B,
    void* __restrict__ Cp, const float* __restrict__ bias,
    int K, int lda, int ldb, int ldc, int m0, int n0)
{
    extern __shared__ char dsm[];
    const uint32_t sA = sptr(dsm);                  // 2 stages x 10240
    const uint32_t sB = sA + 2 * 128 * 40 * 2;      // 2 stages x 20480

    const int tid  = threadIdx.x;
    const int lane = tid & 31;
    const int wid  = tid >> 5;
    const int wm   = (wid & 1) * 64;
    const int wn   = (wid >> 1) * 64;

    float acc[4][8][4];
#pragma unroll
    for (int i = 0; i < 4; i++)
#pragma unroll
        for (int j = 0; j < 8; j++)
#pragma unroll
            for (int t = 0; t < 4; t++) acc[i][j][t] = 0.f;

    // loaders: A 512 16B-units (2/thread), B 1024 units (4/thread)
    const int arow0 = tid >> 2,          acol = (tid & 3) * 8;
    const int brow0 = tid >> 2;

    const __half* Ag = A + (size_t)(m0 + arow0) * lda + acol;
    const __half* Bg = B + (size_t)(n0 + brow0) * ldb + acol;

    auto load_stage = [&](int st, int k0) {
        const uint32_t a = sA + st * 10240;
        const uint32_t b = sB + st * 20480;
        CPA(a + (arow0 * 40 + acol) * 2,        Ag + k0);
        CPA(a + ((arow0 + 64) * 40 + acol) * 2, Ag + (size_t)64 * lda + k0);
#pragma unroll
        for (int u = 0; u < 4; u++)
            CPA(b + ((brow0 + u * 64) * 40 + acol) * 2,
                Bg + (size_t)(u * 64) * ldb + k0);
        CPC();
    };
    load_stage(0, 0);

    // fragment base addresses (bytes)
    const uint32_t a_fb = ((wm + (lane & 15)) * 40 + (lane >> 4) * 8) * 2;
    const uint32_t b_fb = ((wn + (lane & 7) + (lane >> 4) * 8) * 40
                           + ((lane >> 3) & 1) * 8) * 2;

    const int niter = K / 32;
    int buf = 0;
    for (int it = 0; it < niter; ++it) {
        if (it + 1 < niter) { load_stage(buf ^ 1, (it + 1) * 32); CPW1(); }
        else                { CPW0(); }
        __syncthreads();

        const uint32_t ab = sA + buf * 10240 + a_fb;
        const uint32_t bb = sB + buf * 20480 + b_fb;
#pragma unroll
        for (int ks = 0; ks < 2; ++ks) {
            uint32_t a[4][4], bf[4][4];
#pragma unroll
            for (int mi = 0; mi < 4; mi++)
                ldmx4(a[mi], ab + (mi * 16 * 40 + ks * 16) * 2);
#pragma unroll
            for (int nj2 = 0; nj2 < 4; nj2++)
                ldmx4(bf[nj2], bb + (nj2 * 16 * 40 + ks * 16) * 2);
#pragma unroll
            for (int mi = 0; mi < 4; mi++)
#pragma unroll
                for (int nj = 0; nj < 8; nj++)
                    mma16816(acc[mi][nj], a[mi], &bf[nj >> 1][(nj & 1) * 2]);
        }
        __syncthreads();
        buf ^= 1;
    }

    const int g  = lane >> 2;
    const int tg = lane & 3;
#pragma unroll
    for (int mi = 0; mi < 4; mi++) {
#pragma unroll
        for (int nj = 0; nj < 8; nj++) {
            const int r0 = m0 + wm + mi * 16 + g;
            const int cc = n0 + wn + nj * 8 + 2 * tg;
            float* a4 = acc[mi][nj];
            if (HALF_OUT) {
                __half* C = (__half*)Cp;
                *(__half2*)&C[(size_t)r0 * ldc + cc]       = __floats2half2_rn(a4[0], a4[1]);
                *(__half2*)&C[(size_t)(r0 + 8) * ldc + cc] = __floats2half2_rn(a4[2], a4[3]);
            } else {
                float* C = (float*)Cp;
                float b0 = 0.f, b1 = 0.f;
                if (BIAS) { float2 bb = *(const float2*)&bias[cc]; b0 = bb.x; b1 = bb.y; }
                *(float2*)&C[(size_t)r0 * ldc + cc]       = make_float2(a4[0] + b0, a4[1] + b1);
                *(float2*)&C[(size_t)(r0 + 8) * ldc + cc] = make_float2(a4[2] + b0, a4[3] + b1);
            }
        }
    }
}

// 1. qkv[b][m][n] = Wqkv[m,:] . x[b][n,:]   (half out, channel-major)
__global__ void __launch_bounds__(256, 1) k_qkv()
{
    const __half* B = g_xh + (size_t)blockIdx.z * Nn * Cn;
    __half* C = g_qkv + (size_t)blockIdx.z * 1536 * Nn;
    gemm_big<true, false>(g_wqh, B, C, nullptr, 512, 512, 512, Nn,
                          blockIdx.y * 128, blockIdx.x * 256);
}

// 6. out = xca @ Wout^T + bias   (fp32 out)
__global__ void __launch_bounds__(256, 1) k_out(float* __restrict__ out,
                                                const float* __restrict__ bias)
{
    gemm_big<false, true>(g_xca, g_woh, out, bias, 512, 512, 512, 512,
                          blockIdx.y * 128, blockIdx.x * 256);
}

// ---------------------------------------------------------------------------
// fp16 A@B^T legacy GEMM tile 128x128 (64x32 warp tiles) — small GEMMs
// ---------------------------------------------------------------------------
template<bool HALF_OUT, bool BIAS>
__device__ __forceinline__ void gemm_abt_f16(
    const __half* __restrict__ A, const __half* __restrict__ B,
    void* __restrict__ Cp, const float* __restrict__ bias,
    int K, int lda, int ldb, int ldc, int m0, int n0)
{
    __shared__ __half As[2][128 * 40];
    __shared__ __half Bs[2][128 * 40];

    const int tid  = threadIdx.x;
    const int lane = tid & 31;
    const int wid  = tid >> 5;
    const int wm   = (wid & 1) * 64;
    const int wn   = (wid >> 1) * 32;
    const int lrow = tid >> 2;
    const int lcol = (tid & 3) * 8;

    float acc[4][4][4];
#pragma unroll
    for (int i = 0; i < 4; i++)
#pragma unroll
        for (int j = 0; j < 4; j++)
#pragma unroll
            for (int t = 0; t < 4; t++) acc[i][j][t] = 0.f;

    const __half* Ag = A + (size_t)(m0 + lrow) * lda + lcol;
    const __half* Bg = B + (size_t)(n0 + lrow) * ldb + lcol;
    const uint32_t asb = sptr(&As[0][0]);
    const uint32_t bsb = sptr(&Bs[0][0]);
    const uint32_t so  = 128 * 40 * 2;

    auto load_stage = [&](int st, int k0) {
        uint32_t a = asb + st * so, b2 = bsb + st * so;
        CPA(a + (lrow * 40 + lcol) * 2,        Ag + k0);
        CPA(a + ((lrow + 64) * 40 + lcol) * 2, Ag + (size_t)64 * lda + k0);
        CPA(b2 + (lrow * 40 + lcol) * 2,        Bg + k0);
        CPA(b2 + ((lrow + 64) * 40 + lcol) * 2, Bg + (size_t)64 * ldb + k0);
        CPC();
    };
    load_stage(0, 0);

    const uint32_t a_fb = ((wm + (lane & 15)) * 40 + (lane >> 4) * 8) * 2;
    const uint32_t b_fb = ((wn + (lane & 7)) * 40 + ((lane >> 3) & 1) * 8) * 2;

    const int niter = K / 32;
    int buf = 0;
    for (int it = 0; it < niter; ++it) {
        if (it + 1 < niter) { load_stage(buf ^ 1, (it + 1) * 32); CPW1(); }
        else                { CPW0(); }
        __syncthreads();

        const uint32_t ab = asb + buf * so + a_fb;
        const uint32_t bb = bsb + buf * so + b_fb;
#pragma unroll
        for (int ks = 0; ks < 2; ++ks) {
            uint32_t a[4][4], bf[4][2];
#pragma unroll
            for (int mi = 0; mi < 4; mi++)
                ldmx4(a[mi], ab + (mi * 16 * 40 + ks * 16) * 2);
#pragma unroll
            for (int nj = 0; nj < 4; nj++)
                ldmx2(bf[nj], bb + (nj * 8 * 40 + ks * 16) * 2);
#pragma unroll
            for (int mi = 0; mi < 4; mi++)
#pragma unroll
                for (int nj = 0; nj < 4; nj++)
                    mma16816(acc[mi][nj], a[mi], bf[nj]);
        }
        __syncthreads();
        buf ^= 1;
    }

    const int g  = lane >> 2;
    const int tg = lane & 3;
#pragma unroll
    for (int mi = 0; mi < 4; mi++) {
#pragma unroll
        for (int nj = 0; nj < 4; nj++) {
            const int r0 = m0 + wm + mi * 16 + g;
            const int cc = n0 + wn + nj * 8 + 2 * tg;
            float* a4 = acc[mi][nj];
            if (HALF_OUT) {
                __half* C = (__half*)Cp;
                *(__half2*)&C[(size_t)r0 * ldc + cc]       = __floats2half2_rn(a4[0], a4[1]);
                *(__half2*)&C[(size_t)(r0 + 8) * ldc + cc] = __floats2half2_rn(a4[2], a4[3]);
            } else {
                float* C = (float*)Cp;
                float b0 = 0.f, b1 = 0.f;
                if (BIAS) { float2 bb = *(const float2*)&bias[cc]; b0 = bb.x; b1 = bb.y; }
                *(float2*)&C[(size_t)r0 * ldc + cc]       = make_float2(a4[0] + b0, a4[1] + b1);
                *(float2*)&C[(size_t)(r0 + 8) * ldc + cc] = make_float2(a4[2] + b0, a4[3] + b1);
            }
        }
    }
}

// 3. split-K q@k^T partials (fp32 out)
__global__ void __launch_bounds__(256) k_qk()
{
    const int bh = blockIdx.y;
    const __half* qb = g_qkv + ((size_t)(bh >> 2) * 1536 + (bh & 3) * DHn) * Nn
                     + blockIdx.x * 512;
    const __half* kb = qb + (size_t)512 * Nn;
    float* C = g_attnP + ((size_t)bh * QK_SPLIT + blockIdx.x) * (DHn * DHn);
    gemm_abt_f16<false, false>(qb, kb, C, nullptr, 512, Nn, Nn, DHn, 0, 0);
}

// 5. xca = v_t @ attn^T (half out, token-major)
__global__ void __launch_bounds__(256) k_av()
{
    const int bh = blockIdx.z;
    const int b = bh >> 2, h = bh & 3;
    const __half* A  = g_vt  + (size_t)b * Nn * Cn + h * DHn;
    const __half* Bt = g_attn + (size_t)bh * DHn * DHn;
    __half* C = g_xca + (size_t)b * Nn * Cn + h * DHn;
    gemm_abt_f16<true, false>(A, Bt, C, nullptr, 128, 512, 128, 512,
                              blockIdx.y * 128, 0);
}

// ---------------- small kernels ---------------------------------------------
__global__ void __launch_bounds__(256) f2h(const float* __restrict__ s,
                                           __half* __restrict__ d, int n4)
{
    const int i = blockIdx.x * 256 + threadIdx.x;
    if (i < n4) {
        float4 v = ((const float4*)s)[i];
        ((__half2*)d)[i * 2]     = __floats2half2_rn(v.x, v.y);
        ((__half2*)d)[i * 2 + 1] = __floats2half2_rn(v.z, v.w);
    }
}

__global__ void __launch_bounds__(256) norm_kernel()
{
    const int b = blockIdx.x >> 10;
    const int m = blockIdx.x & 1023;
    const __half2* row = (const __half2*)(g_qkv + ((size_t)b * 1536 + m) * Nn);
    float ss = 0.f;
    for (int i = threadIdx.x; i < Nn / 2; i += 256) {
        float2 f = __half22float2(row[i]);
        ss = fmaf(f.x, f.x, fmaf(f.y, f.y, ss));
    }
    __shared__ float red[256];
    red[threadIdx.x] = ss;
    __syncthreads();
    for (int off = 128; off; off >>= 1) {
        if (threadIdx.x < off) red[threadIdx.x] += red[threadIdx.x + off];
        __syncthreads();
    }
    if (threadIdx.x == 0)
        g_inv[b * 1024 + m] = 1.f / fmaxf(sqrtf(red[0]), 1e-12f);
}

__global__ void __launch_bounds__(256) vtrans()
{
    __shared__ __half ts[32][33];
    const int n0 = blockIdx.x * 32, hd0 = blockIdx.y * 32, b = blockIdx.z;
    const int tx = threadIdx.x, ty = threadIdx.y;
    const __half* src = g_qkv + ((size_t)b * 1536 + 1024 + hd0) * Nn + n0;
#pragma unroll
    for (int r = 0; r < 4; r++)
        ts[ty + r * 8][tx] = src[(size_t)(ty + r * 8) * Nn + tx];
    __syncthreads();
    __half* dst = g_vt + ((size_t)b * Nn + n0) * Cn + hd0;
#pragma unroll
    for (int r = 0; r < 4; r++)
        dst[(size_t)(ty + r * 8) * Cn + tx] = ts[tx][ty + r * 8];
}

__global__ void __launch_bounds__(128) softmax_kernel(const float* __restrict__ temp)
{
    const int bh = blockIdx.x >> 7;
    const int c  = blockIdx.x & 127;
    const int b  = bh >> 2, h = bh & 3;
    const int d  = threadIdx.x;

    const float* base = g_attnP + (size_t)bh * QK_SPLIT * (DHn * DHn) + c * DHn + d;
    float s = 0.f;
#pragma unroll
    for (int p = 0; p < QK_SPLIT; p++) s += base[(size_t)p * (DHn * DHn)];

    const float qinv = g_inv[b * 1024 + h * DHn + c];
    const float kinv = g_inv[b * 1024 + 512 + h * DHn + d];
    const float val  = s * qinv * kinv * temp[h];

    __shared__ float red[128];
    red[d] = val;
    __syncthreads();
    for (int off = 64; off; off >>= 1) {
        if (d < off) red[d] = fmaxf(red[d], red[d + off]);
        __syncthreads();
    }
    const float mx = red[0];
    __syncthreads();
    const float e = expf(val - mx);
    red[d] = e;
    __syncthreads();
    for (int off = 64; off; off >>= 1) {
        if (d < off) red[d] += red[d + off];
        __syncthreads();
    }
    g_attn[(size_t)bh * (DHn * DHn) + c * DHn + d] = __float2half_rn(e / red[0]);
}

// ---------------------------------------------------------------------------
extern "C" void kernel_launch(void* const* d_in, const int* in_sizes, int n_in,
                              void* d_out, int out_size)
{
    const float* x    = (const float*)d_in[0];
    const float* Wqkv = (const float*)d_in[1];
    const float* Wout = (const float*)d_in[2];
    const float* bout = (const float*)d_in[3];
    const float* temp = (const float*)d_in[4];
    float* out = (float*)d_out;

    __half *xh, *wqh, *woh;
    cudaGetSymbolAddress((void**)&xh,  g_xh);
    cudaGetSymbolAddress((void**)&wqh, g_wqh);
    cudaGetSymbolAddress((void**)&woh, g_woh);

    cudaFuncSetAttribute(k_qkv, cudaFuncAttributeMaxDynamicSharedMemorySize, BIG_SMEM);
    cudaFuncSetAttribute(k_out, cudaFuncAttributeMaxDynamicSharedMemorySize, BIG_SMEM);

    // 0. fp32 -> fp16 conversions
    f2h<<<(Bn * Nn * Cn / 4 + 255) / 256, 256>>>(x, xh, Bn * Nn * Cn / 4);
    f2h<<<(1536 * 512 / 4 + 255) / 256, 256>>>(Wqkv, wqh, 1536 * 512 / 4);
    f2h<<<(512 * 512 / 4 + 255) / 256, 256>>>(Wout, woh, 512 * 512 / 4);

    // 1. QKV GEMM (big tiles), channel-major output
    k_qkv<<<dim3(32, 12, 4), 256, BIG_SMEM>>>();

    // 2. inverse L2 norms
    norm_kernel<<<Bn * 1024, 256>>>();

    // 2b. v transpose to token-major
    vtrans<<<dim3(Nn / 32, 16, Bn), dim3(32, 8)>>>();

    // 3. split-K q@k^T partials
    k_qk<<<dim3(QK_SPLIT, 16), 256>>>();

    // 4. reduce + scale + softmax
    softmax_kernel<<<16 * 128, 128>>>(temp);

    // 5. xca = attn @ v (token-major output)
    k_av<<<dim3(1, 64, 16), 256>>>();

    // 6. out = xca @ Wout^T + bias (big tiles)
    k_out<<<dim3(2, 256), 256, BIG_SMEM>>>(out, bout);
}

// round 6
// speedup vs baseline: 1.1665x; 1.1665x over previous
#include <cuda_runtime.h>
#include <cuda_fp16.h>
#include <cstddef>
#include <cstdint>

#define Bn   4
#define Nn   8192
#define Cn   512
#define DHn  128
#define QK_SPLIT 16

// ---------------- scratch (device globals) ---------------------------------
__device__ __align__(128) __half g_xh  [(size_t)Bn * Nn * Cn];
__device__ __align__(128) __half g_wqh [1536 * 512];
__device__ __align__(128) __half g_woh [512 * 512];
__device__ __align__(128) __half g_qkv [(size_t)Bn * 1536 * Nn];   // channel-major
__device__ __align__(128) __half g_vt  [(size_t)Bn * Nn * Cn];     // v token-major
__device__ __align__(128) float  g_inv [Bn * 1024];
__device__ __align__(128) float  g_attnP[16 * QK_SPLIT * DHn * DHn];
__device__ __align__(128) __half g_attn [16 * DHn * DHn];
__device__ __align__(128) __half g_xca [(size_t)Bn * Nn * Cn];

// ---------------- PTX helpers ----------------------------------------------
__device__ __forceinline__ uint32_t sptr(const void* p) {
    return (uint32_t)__cvta_generic_to_shared(p);
}
#define CPA(dst, src) asm volatile("cp.async.ca.shared.global [%0],[%1],16;\n" \
                                   :: "r"(dst), "l"(src))
#define CPC() asm volatile("cp.async.commit_group;\n")
#define CPW0() asm volatile("cp.async.wait_group 0;\n")
#define CPW1() asm volatile("cp.async.wait_group 1;\n")

__device__ __forceinline__ void ldmx4(uint32_t* r, uint32_t a) {
    asm volatile("ldmatrix.sync.aligned.m8n8.x4.shared.b16 {%0,%1,%2,%3},[%4];"
                 : "=r"(r[0]), "=r"(r[1]), "=r"(r[2]), "=r"(r[3]) : "r"(a));
}
__device__ __forceinline__ void ldmx2(uint32_t* r, uint32_t a) {
    asm volatile("ldmatrix.sync.aligned.m8n8.x2.shared.b16 {%0,%1},[%2];"
                 : "=r"(r[0]), "=r"(r[1]) : "r"(a));
}
__device__ __forceinline__ void mma16816(float* c, const uint32_t* a, const uint32_t* b) {
    asm volatile(
        "mma.sync.aligned.m16n8k16.row.col.f32.f16.f16.f32 "
        "{%0,%1,%2,%3},{%4,%5,%6,%7},{%8,%9},{%0,%1,%2,%3};"
        : "+f"(c[0]), "+f"(c[1]), "+f"(c[2]), "+f"(c[3])
        : "r"(a[0]), "r"(a[1]), "r"(a[2]), "r"(a[3]), "r"(b[0]), "r"(b[1]));
}

// ---------------------------------------------------------------------------
// PIPELINED BIG TILE fp16 A@B^T GEMM: CTA 128(m) x 256(n), 8 warps, 64x64
// warp tiles, BK=32, 3-stage cp.async ring, fragment double buffering.
// A[m,:K], B[n,:K] K-contiguous fp16, fp32 accumulate. Requires K/32 >= 2.
// ---------------------------------------------------------------------------
#define STAGE_BYTES (128 * 40 * 2 + 256 * 40 * 2)   // 30720
#define BIG_SMEM    (3 * STAGE_BYTES)               // 92160

template<bool HALF_OUT, bool BIAS>
__device__ __forceinline__ void gemm_big(
    const __half* __restrict__ A, const __half* __restrict__ B,
    void* __restrict__ Cp, const float* __restrict__ bias,
    int K, int lda, int ldb, int ldc, int m0, int n0)
{
    extern __shared__ char dsm[];
    const uint32_t s0 = sptr(dsm);

    const int tid  = threadIdx.x;
    const int lane = tid & 31;
    const int wid  = tid >> 5;
    const int wm   = (wid & 1) * 64;
    const int wn   = (wid >> 1) * 64;

    float acc[4][8][4];
#pragma unroll
    for (int i = 0; i < 4; i++)
#pragma unroll
        for (int j = 0; j < 8; j++)
#pragma unroll
            for (int t = 0; t < 4; t++) acc[i][j][t] = 0.f;

    const int arow0 = tid >> 2, acol = (tid & 3) * 8;

    const __half* Ag = A + (size_t)(m0 + arow0) * lda + acol;
    const __half* Bg = B + (size_t)(n0 + arow0) * ldb + acol;

    auto load_stage = [&](int st, int k0) {
        const uint32_t a = s0 + st * STAGE_BYTES;
        const uint32_t b = a + 128 * 40 * 2;
        CPA(a + (arow0 * 40 + acol) * 2,        Ag + k0);
        CPA(a + ((arow0 + 64) * 40 + acol) * 2, Ag + (size_t)64 * lda + k0);
#pragma unroll
        for (int u = 0; u < 4; u++)
            CPA(b + ((arow0 + u * 64) * 40 + acol) * 2,
                Bg + (size_t)(u * 64) * ldb + k0);
        CPC();
    };

    // fragment base offsets within a stage (bytes)
    const uint32_t a_fb = ((wm + (lane & 15)) * 40 + (lane >> 4) * 8) * 2;
    const uint32_t b_fb = 128 * 40 * 2 +
        ((wn + (lane & 7) + (lane >> 4) * 8) * 40 + ((lane >> 3) & 1) * 8) * 2;

    uint32_t af[2][4][4], bf[2][4][4];

    auto ldfrags = [&](int slot, int st, int ks) {
        const uint32_t ab = s0 + st * STAGE_BYTES + a_fb + ks * 32;
        const uint32_t bb = s0 + st * STAGE_BYTES + b_fb + ks * 32;
#pragma unroll
        for (int mi = 0; mi < 4; mi++)
            ldmx4(af[slot][mi], ab + mi * 16 * 80);
#pragma unroll
        for (int nj = 0; nj < 4; nj++)
            ldmx4(bf[slot][nj], bb + nj * 16 * 80);
    };
    auto mma_all = [&](int slot) {
#pragma unroll
        for (int mi = 0; mi < 4; mi++)
#pragma unroll
            for (int nj = 0; nj < 8; nj++)
                mma16816(acc[mi][nj], af[slot][mi], &bf[slot][nj >> 1][(nj & 1) * 2]);
    };

    const int niter = K / 32;
    // prologue: stages 0,1 in flight; consume stage 0 frags (ks=0)
    load_stage(0, 0);
    load_stage(1, 32);
    CPW1();
    __syncthreads();
    ldfrags(0, 0, 0);

    int st = 0;
    for (int it = 0; it < niter; ++it) {
        // ---- phase ks=0: prefetch ks=1 frags, issue global loads, compute
        ldfrags(1, st, 1);
        if (it + 2 < niter) load_stage((st + 2) % 3, (it + 2) * 32);
        mma_all(0);
        // ---- phase ks=1: make next stage visible, prefetch its ks=0 frags
        if (it + 1 < niter) {
            if (it + 2 < niter) { CPW1(); } else { CPW0(); }
            __syncthreads();
            const int nst = (st + 1 == 3) ? 0 : st + 1;
            ldfrags(0, nst, 0);
            st = nst;
        }
        mma_all(1);
    }

    const int g  = lane >> 2;
    const int tg = lane & 3;
#pragma unroll
    for (int mi = 0; mi < 4; mi++) {
#pragma unroll
        for (int nj = 0; nj < 8; nj++) {
            const int r0 = m0 + wm + mi * 16 + g;
            const int cc = n0 + wn + nj * 8 + 2 * tg;
            float* a4 = acc[mi][nj];
            if (HALF_OUT) {
                __half* C = (__half*)Cp;
                *(__half2*)&C[(size_t)r0 * ldc + cc]       = __floats2half2_rn(a4[0], a4[1]);
                *(__half2*)&C[(size_t)(r0 + 8) * ldc + cc] = __floats2half2_rn(a4[2], a4[3]);
            } else {
                float* C = (float*)Cp;
                float b0 = 0.f, b1 = 0.f;
                if (BIAS) { float2 bb = *(const float2*)&bias[cc]; b0 = bb.x; b1 = bb.y; }
                *(float2*)&C[(size_t)r0 * ldc + cc]       = make_float2(a4[0] + b0, a4[1] + b1);
                *(float2*)&C[(size_t)(r0 + 8) * ldc + cc] = make_float2(a4[2] + b0, a4[3] + b1);
            }
        }
    }
}

// 1. qkv[b][m][n] = Wqkv[m,:] . x[b][n,:]   (half out, channel-major)
__global__ void __launch_bounds__(256, 1) k_qkv()
{
    const __half* B = g_xh + (size_t)blockIdx.z * Nn * Cn;
    __half* C = g_qkv + (size_t)blockIdx.z * 1536 * Nn;
    gemm_big<true, false>(g_wqh, B, C, nullptr, 512, 512, 512, Nn,
                          blockIdx.y * 128, blockIdx.x * 256);
}

// 6. out = xca @ Wout^T + bias   (fp32 out)
__global__ void __launch_bounds__(256, 1) k_out(float* __restrict__ out,
                                                const float* __restrict__ bias)
{
    gemm_big<false, true>(g_xca, g_woh, out, bias, 512, 512, 512, 512,
                          blockIdx.y * 128, blockIdx.x * 256);
}

// ---------------------------------------------------------------------------
// fp16 A@B^T legacy GEMM tile 128x128 (64x32 warp tiles) — small GEMMs
// ---------------------------------------------------------------------------
template<bool HALF_OUT, bool BIAS>
__device__ __forceinline__ void gemm_abt_f16(
    const __half* __restrict__ A, const __half* __restrict__ B,
    void* __restrict__ Cp, const float* __restrict__ bias,
    int K, int lda, int ldb, int ldc, int m0, int n0)
{
    __shared__ __half As[2][128 * 40];
    __shared__ __half Bs[2][128 * 40];

    const int tid  = threadIdx.x;
    const int lane = tid & 31;
    const int wid  = tid >> 5;
    const int wm   = (wid & 1) * 64;
    const int wn   = (wid >> 1) * 32;
    const int lrow = tid >> 2;
    const int lcol = (tid & 3) * 8;

    float acc[4][4][4];
#pragma unroll
    for (int i = 0; i < 4; i++)
#pragma unroll
        for (int j = 0; j < 4; j++)
#pragma unroll
            for (int t = 0; t < 4; t++) acc[i][j][t] = 0.f;

    const __half* Ag = A + (size_t)(m0 + lrow) * lda + lcol;
    const __half* Bg = B + (size_t)(n0 + lrow) * ldb + lcol;
    const uint32_t asb = sptr(&As[0][0]);
    const uint32_t bsb = sptr(&Bs[0][0]);
    const uint32_t so  = 128 * 40 * 2;

    auto load_stage = [&](int st, int k0) {
        uint32_t a = asb + st * so, b2 = bsb + st * so;
        CPA(a + (lrow * 40 + lcol) * 2,        Ag + k0);
        CPA(a + ((lrow + 64) * 40 + lcol) * 2, Ag + (size_t)64 * lda + k0);
        CPA(b2 + (lrow * 40 + lcol) * 2,        Bg + k0);
        CPA(b2 + ((lrow + 64) * 40 + lcol) * 2, Bg + (size_t)64 * ldb + k0);
        CPC();
    };
    load_stage(0, 0);

    const uint32_t a_fb = ((wm + (lane & 15)) * 40 + (lane >> 4) * 8) * 2;
    const uint32_t b_fb = ((wn + (lane & 7)) * 40 + ((lane >> 3) & 1) * 8) * 2;

    const int niter = K / 32;
    int buf = 0;
    for (int it = 0; it < niter; ++it) {
        if (it + 1 < niter) { load_stage(buf ^ 1, (it + 1) * 32); CPW1(); }
        else                { CPW0(); }
        __syncthreads();

        const uint32_t ab = asb + buf * so + a_fb;
        const uint32_t bb = bsb + buf * so + b_fb;
#pragma unroll
        for (int ks = 0; ks < 2; ++ks) {
            uint32_t a[4][4], bfr[4][2];
#pragma unroll
            for (int mi = 0; mi < 4; mi++)
                ldmx4(a[mi], ab + (mi * 16 * 40 + ks * 16) * 2);
#pragma unroll
            for (int nj = 0; nj < 4; nj++)
                ldmx2(bfr[nj], bb + (nj * 8 * 40 + ks * 16) * 2);
#pragma unroll
            for (int mi = 0; mi < 4; mi++)
#pragma unroll
                for (int nj = 0; nj < 4; nj++)
                    mma16816(acc[mi][nj], a[mi], bfr[nj]);
        }
        __syncthreads();
        buf ^= 1;
    }

    const int g  = lane >> 2;
    const int tg = lane & 3;
#pragma unroll
    for (int mi = 0; mi < 4; mi++) {
#pragma unroll
        for (int nj = 0; nj < 4; nj++) {
            const int r0 = m0 + wm + mi * 16 + g;
            const int cc = n0 + wn + nj * 8 + 2 * tg;
            float* a4 = acc[mi][nj];
            if (HALF_OUT) {
                __half* C = (__half*)Cp;
                *(__half2*)&C[(size_t)r0 * ldc + cc]       = __floats2half2_rn(a4[0], a4[1]);
                *(__half2*)&C[(size_t)(r0 + 8) * ldc + cc] = __floats2half2_rn(a4[2], a4[3]);
            } else {
                float* C = (float*)Cp;
                float b0 = 0.f, b1 = 0.f;
                if (BIAS) { float2 bb = *(const float2*)&bias[cc]; b0 = bb.x; b1 = bb.y; }
                *(float2*)&C[(size_t)r0 * ldc + cc]       = make_float2(a4[0] + b0, a4[1] + b1);
                *(float2*)&C[(size_t)(r0 + 8) * ldc + cc] = make_float2(a4[2] + b0, a4[3] + b1);
            }
        }
    }
}

// 3. split-K q@k^T partials (fp32 out)
__global__ void __launch_bounds__(256) k_qk()
{
    const int bh = blockIdx.y;
    const __half* qb = g_qkv + ((size_t)(bh >> 2) * 1536 + (bh & 3) * DHn) * Nn
                     + blockIdx.x * 512;
    const __half* kb = qb + (size_t)512 * Nn;
    float* C = g_attnP + ((size_t)bh * QK_SPLIT + blockIdx.x) * (DHn * DHn);
    gemm_abt_f16<false, false>(qb, kb, C, nullptr, 512, Nn, Nn, DHn, 0, 0);
}

// 5. xca = v_t @ attn^T (half out, token-major)
__global__ void __launch_bounds__(256) k_av()
{
    const int bh = blockIdx.z;
    const int b = bh >> 2, h = bh & 3;
    const __half* A  = g_vt  + (size_t)b * Nn * Cn + h * DHn;
    const __half* Bt = g_attn + (size_t)bh * DHn * DHn;
    __half* C = g_xca + (size_t)b * Nn * Cn + h * DHn;
    gemm_abt_f16<true, false>(A, Bt, C, nullptr, 128, 512, 128, 512,
                              blockIdx.y * 128, 0);
}

// ---------------- small kernels ---------------------------------------------
__global__ void __launch_bounds__(256) f2h(const float* __restrict__ s,
                                           __half* __restrict__ d, int n4)
{
    const int i = blockIdx.x * 256 + threadIdx.x;
    if (i < n4) {
        float4 v = ((const float4*)s)[i];
        ((__half2*)d)[i * 2]     = __floats2half2_rn(v.x, v.y);
        ((__half2*)d)[i * 2 + 1] = __floats2half2_rn(v.z, v.w);
    }
}

__global__ void __launch_bounds__(256) norm_kernel()
{
    const int b = blockIdx.x >> 10;
    const int m = blockIdx.x & 1023;
    const __half2* row = (const __half2*)(g_qkv + ((size_t)b * 1536 + m) * Nn);
    float ss = 0.f;
    for (int i = threadIdx.x; i < Nn / 2; i += 256) {
        float2 f = __half22float2(row[i]);
        ss = fmaf(f.x, f.x, fmaf(f.y, f.y, ss));
    }
    __shared__ float red[256];
    red[threadIdx.x] = ss;
    __syncthreads();
    for (int off = 128; off; off >>= 1) {
        if (threadIdx.x < off) red[threadIdx.x] += red[threadIdx.x + off];
        __syncthreads();
    }
    if (threadIdx.x == 0)
        g_inv[b * 1024 + m] = 1.f / fmaxf(sqrtf(red[0]), 1e-12f);
}

__global__ void __launch_bounds__(256) vtrans()
{
    __shared__ __half ts[32][33];
    const int n0 = blockIdx.x * 32, hd0 = blockIdx.y * 32, b = blockIdx.z;
    const int tx = threadIdx.x, ty = threadIdx.y;
    const __half* src = g_qkv + ((size_t)b * 1536 + 1024 + hd0) * Nn + n0;
#pragma unroll
    for (int r = 0; r < 4; r++)
        ts[ty + r * 8][tx] = src[(size_t)(ty + r * 8) * Nn + tx];
    __syncthreads();
    __half* dst = g_vt + ((size_t)b * Nn + n0) * Cn + hd0;
#pragma unroll
    for (int r = 0; r < 4; r++)
        dst[(size_t)(ty + r * 8) * Cn + tx] = ts[tx][ty + r * 8];
}

__global__ void __launch_bounds__(128) softmax_kernel(const float* __restrict__ temp)
{
    const int bh = blockIdx.x >> 7;
    const int c  = blockIdx.x & 127;
    const int b  = bh >> 2, h = bh & 3;
    const int d  = threadIdx.x;

    const float* base = g_attnP + (size_t)bh * QK_SPLIT * (DHn * DHn) + c * DHn + d;
    float s = 0.f;
#pragma unroll
    for (int p = 0; p < QK_SPLIT; p++) s += base[(size_t)p * (DHn * DHn)];

    const float qinv = g_inv[b * 1024 + h * DHn + c];
    const float kinv = g_inv[b * 1024 + 512 + h * DHn + d];
    const float val  = s * qinv * kinv * temp[h];

    __shared__ float red[128];
    red[d] = val;
    __syncthreads();
    for (int off = 64; off; off >>= 1) {
        if (d < off) red[d] = fmaxf(red[d], red[d + off]);
        __syncthreads();
    }
    const float mx = red[0];
    __syncthreads();
    const float e = expf(val - mx);
    red[d] = e;
    __syncthreads();
    for (int off = 64; off; off >>= 1) {
        if (d < off) red[d] += red[d + off];
        __syncthreads();
    }
    g_attn[(size_t)bh * (DHn * DHn) + c * DHn + d] = __float2half_rn(e / red[0]);
}

// ---------------------------------------------------------------------------
extern "C" void kernel_launch(void* const* d_in, const int* in_sizes, int n_in,
                              void* d_out, int out_size)
{
    const float* x    = (const float*)d_in[0];
    const float* Wqkv = (const float*)d_in[1];
    const float* Wout = (const float*)d_in[2];
    const float* bout = (const float*)d_in[3];
    const float* temp = (const float*)d_in[4];
    float* out = (float*)d_out;

    __half *xh, *wqh, *woh;
    cudaGetSymbolAddress((void**)&xh,  g_xh);
    cudaGetSymbolAddress((void**)&wqh, g_wqh);
    cudaGetSymbolAddress((void**)&woh, g_woh);

    cudaFuncSetAttribute(k_qkv, cudaFuncAttributeMaxDynamicSharedMemorySize, BIG_SMEM);
    cudaFuncSetAttribute(k_out, cudaFuncAttributeMaxDynamicSharedMemorySize, BIG_SMEM);

    // 0. fp32 -> fp16 conversions
    f2h<<<(Bn * Nn * Cn / 4 + 255) / 256, 256>>>(x, xh, Bn * Nn * Cn / 4);
    f2h<<<(1536 * 512 / 4 + 255) / 256, 256>>>(Wqkv, wqh, 1536 * 512 / 4);
    f2h<<<(512 * 512 / 4 + 255) / 256, 256>>>(Wout, woh, 512 * 512 / 4);

    // 1. QKV GEMM (pipelined big tiles), channel-major output
    k_qkv<<<dim3(32, 12, 4), 256, BIG_SMEM>>>();

    // 2. inverse L2 norms
    norm_kernel<<<Bn * 1024, 256>>>();

    // 2b. v transpose to token-major
    vtrans<<<dim3(Nn / 32, 16, Bn), dim3(32, 8)>>>();

    // 3. split-K q@k^T partials
    k_qk<<<dim3(QK_SPLIT, 16), 256>>>();

    // 4. reduce + scale + softmax
    softmax_kernel<<<16 * 128, 128>>>(temp);

    // 5. xca = attn @ v (token-major output)
    k_av<<<dim3(1, 64, 16), 256>>>();

    // 6. out = xca @ Wout^T + bias (pipelined big tiles)
    k_out<<<dim3(2, 256), 256, BIG_SMEM>>>(out, bout);
}

// round 7
// speedup vs baseline: 1.2261x; 1.0511x over previous
#include <cuda_runtime.h>
#include <cuda_fp16.h>
#include <cstddef>
#include <cstdint>

#define Bn   4
#define Nn   8192
#define Cn   512
#define DHn  128
#define QK_SPLIT 16

// ---------------- scratch (device globals) ---------------------------------
__device__ __align__(128) __half g_xh  [(size_t)Bn * Nn * Cn];
__device__ __align__(128) __half g_wqh [1536 * 512];
__device__ __align__(128) __half g_woh [512 * 512];
__device__ __align__(128) __half g_qkv [(size_t)Bn * 1536 * Nn];   // channel-major
__device__ __align__(128) __half g_vt  [(size_t)Bn * Nn * Cn];     // v token-major
__device__ __align__(128) float  g_inv [Bn * 1024];
__device__ __align__(128) float  g_attnP[16 * QK_SPLIT * DHn * DHn];
__device__ __align__(128) __half g_attn [16 * DHn * DHn];
__device__ __align__(128) __half g_xca [(size_t)Bn * Nn * Cn];

// ---------------- PTX helpers ----------------------------------------------
__device__ __forceinline__ uint32_t sptr(const void* p) {
    return (uint32_t)__cvta_generic_to_shared(p);
}
#define CPA(dst, src) asm volatile("cp.async.ca.shared.global [%0],[%1],16;\n" \
                                   :: "r"(dst), "l"(src))
#define CPC() asm volatile("cp.async.commit_group;\n")
#define CPW0() asm volatile("cp.async.wait_group 0;\n")
#define CPW1() asm volatile("cp.async.wait_group 1;\n")

__device__ __forceinline__ void ldmx4(uint32_t* r, uint32_t a) {
    asm volatile("ldmatrix.sync.aligned.m8n8.x4.shared.b16 {%0,%1,%2,%3},[%4];"
                 : "=r"(r[0]), "=r"(r[1]), "=r"(r[2]), "=r"(r[3]) : "r"(a));
}
__device__ __forceinline__ void ldmx2(uint32_t* r, uint32_t a) {
    asm volatile("ldmatrix.sync.aligned.m8n8.x2.shared.b16 {%0,%1},[%2];"
                 : "=r"(r[0]), "=r"(r[1]) : "r"(a));
}
__device__ __forceinline__ void mma16816(float* c, const uint32_t* a, const uint32_t* b) {
    asm volatile(
        "mma.sync.aligned.m16n8k16.row.col.f32.f16.f16.f32 "
        "{%0,%1,%2,%3},{%4,%5,%6,%7},{%8,%9},{%0,%1,%2,%3};"
        : "+f"(c[0]), "+f"(c[1]), "+f"(c[2]), "+f"(c[3])
        : "r"(a[0]), "r"(a[1]), "r"(a[2]), "r"(a[3]), "r"(b[0]), "r"(b[1]));
}

// ---------------------------------------------------------------------------
// PIPELINED fp16 A@B^T GEMM: CTA 128(m) x 128(n), 128 threads (4 warps,
// 64x64 warp tiles), BK=32, 3-stage cp.async ring, fragment double buffering.
// 2 CTAs per SM. A[m,:K], B[n,:K] K-contiguous fp16, fp32 acc. K/32 >= 2.
// ---------------------------------------------------------------------------
#define STAGE_BYTES (128 * 40 * 2 + 128 * 40 * 2)   // 20480
#define BIG_SMEM    (3 * STAGE_BYTES)               // 61440

template<bool HALF_OUT, bool BIAS>
__device__ __forceinline__ void gemm_big(
    const __half* __restrict__ A, const __half* __restrict__ B,
    void* __restrict__ Cp, const float* __restrict__ bias,
    int K, int lda, int ldb, int ldc, int m0, int n0)
{
    extern __shared__ char dsm[];
    const uint32_t s0 = sptr(dsm);

    const int tid  = threadIdx.x;
    const int lane = tid & 31;
    const int wid  = tid >> 5;
    const int wm   = (wid & 1) * 64;
    const int wn   = (wid >> 1) * 64;

    float acc[4][8][4];
#pragma unroll
    for (int i = 0; i < 4; i++)
#pragma unroll
        for (int j = 0; j < 8; j++)
#pragma unroll
            for (int t = 0; t < 4; t++) acc[i][j][t] = 0.f;

    // loaders: per stage each matrix = 128 rows x 32 halves = 512 16B-chunks
    // 128 threads x 4 chunks each per matrix
    const int lrow = tid >> 2;           // 0..31 base row group
    const int lc8  = (tid & 3) * 8;      // half offset within 32

    const __half* Ag = A + (size_t)(m0 + lrow) * lda + lc8;
    const __half* Bg = B + (size_t)(n0 + lrow) * ldb + lc8;

    auto load_stage = [&](int st, int k0) {
        const uint32_t a = s0 + st * STAGE_BYTES;
        const uint32_t b = a + 128 * 40 * 2;
#pragma unroll
        for (int u = 0; u < 4; u++) {
            CPA(a + ((lrow + u * 32) * 40 + lc8) * 2,
                Ag + (size_t)(u * 32) * lda + k0);
            CPA(b + ((lrow + u * 32) * 40 + lc8) * 2,
                Bg + (size_t)(u * 32) * ldb + k0);
        }
        CPC();
    };

    // fragment base offsets within a stage (bytes)
    const uint32_t a_fb = ((wm + (lane & 15)) * 40 + (lane >> 4) * 8) * 2;
    const uint32_t b_fb = 128 * 40 * 2 +
        ((wn + (lane & 7) + (lane >> 4) * 8) * 40 + ((lane >> 3) & 1) * 8) * 2;

    uint32_t af[2][4][4], bf[2][4][4];

    auto ldfrags = [&](int slot, int st, int ks) {
        const uint32_t ab = s0 + st * STAGE_BYTES + a_fb + ks * 32;
        const uint32_t bb = s0 + st * STAGE_BYTES + b_fb + ks * 32;
#pragma unroll
        for (int mi = 0; mi < 4; mi++)
            ldmx4(af[slot][mi], ab + mi * 16 * 80);
#pragma unroll
        for (int nj = 0; nj < 4; nj++)
            ldmx4(bf[slot][nj], bb + nj * 16 * 80);
    };
    auto mma_all = [&](int slot) {
#pragma unroll
        for (int mi = 0; mi < 4; mi++)
#pragma unroll
            for (int nj = 0; nj < 8; nj++)
                mma16816(acc[mi][nj], af[slot][mi], &bf[slot][nj >> 1][(nj & 1) * 2]);
    };

    const int niter = K / 32;
    // prologue: stages 0,1 in flight; consume stage 0 frags (ks=0)
    load_stage(0, 0);
    load_stage(1, 32);
    CPW1();
    __syncthreads();
    ldfrags(0, 0, 0);

    int st = 0;
    for (int it = 0; it < niter; ++it) {
        // ---- phase ks=0: prefetch ks=1 frags, issue global loads, compute
        ldfrags(1, st, 1);
        if (it + 2 < niter) load_stage((st + 2) % 3, (it + 2) * 32);
        mma_all(0);
        // ---- phase ks=1: make next stage visible, prefetch its ks=0 frags
        if (it + 1 < niter) {
            if (it + 2 < niter) { CPW1(); } else { CPW0(); }
            __syncthreads();
            const int nst = (st + 1 == 3) ? 0 : st + 1;
            ldfrags(0, nst, 0);
            st = nst;
        }
        mma_all(1);
    }

    const int g  = lane >> 2;
    const int tg = lane & 3;
#pragma unroll
    for (int mi = 0; mi < 4; mi++) {
#pragma unroll
        for (int nj = 0; nj < 8; nj++) {
            const int r0 = m0 + wm + mi * 16 + g;
            const int cc = n0 + wn + nj * 8 + 2 * tg;
            float* a4 = acc[mi][nj];
            if (HALF_OUT) {
                __half* C = (__half*)Cp;
                *(__half2*)&C[(size_t)r0 * ldc + cc]       = __floats2half2_rn(a4[0], a4[1]);
                *(__half2*)&C[(size_t)(r0 + 8) * ldc + cc] = __floats2half2_rn(a4[2], a4[3]);
            } else {
                float* C = (float*)Cp;
                float b0 = 0.f, b1 = 0.f;
                if (BIAS) { float2 bb = *(const float2*)&bias[cc]; b0 = bb.x; b1 = bb.y; }
                *(float2*)&C[(size_t)r0 * ldc + cc]       = make_float2(a4[0] + b0, a4[1] + b1);
                *(float2*)&C[(size_t)(r0 + 8) * ldc + cc] = make_float2(a4[2] + b0, a4[3] + b1);
            }
        }
    }
}

// 1. qkv[b][m][n] = Wqkv[m,:] . x[b][n,:]   (half out, channel-major)
__global__ void __launch_bounds__(128, 2) k_qkv()
{
    const __half* B = g_xh + (size_t)blockIdx.z * Nn * Cn;
    __half* C = g_qkv + (size_t)blockIdx.z * 1536 * Nn;
    gemm_big<true, false>(g_wqh, B, C, nullptr, 512, 512, 512, Nn,
                          blockIdx.y * 128, blockIdx.x * 128);
}

// 6. out = xca @ Wout^T + bias   (fp32 out)
__global__ void __launch_bounds__(128, 2) k_out(float* __restrict__ out,
                                                const float* __restrict__ bias)
{
    gemm_big<false, true>(g_xca, g_woh, out, bias, 512, 512, 512, 512,
                          blockIdx.y * 128, blockIdx.x * 128);
}

// ---------------------------------------------------------------------------
// fp16 A@B^T legacy GEMM tile 128x128 (64x32 warp tiles) — small GEMMs
// ---------------------------------------------------------------------------
template<bool HALF_OUT, bool BIAS>
__device__ __forceinline__ void gemm_abt_f16(
    const __half* __restrict__ A, const __half* __restrict__ B,
    void* __restrict__ Cp, const float* __restrict__ bias,
    int K, int lda, int ldb, int ldc, int m0, int n0)
{
    __shared__ __half As[2][128 * 40];
    __shared__ __half Bs[2][128 * 40];

    const int tid  = threadIdx.x;
    const int lane = tid & 31;
    const int wid  = tid >> 5;
    const int wm   = (wid & 1) * 64;
    const int wn   = (wid >> 1) * 32;
    const int lrow = tid >> 2;
    const int lcol = (tid & 3) * 8;

    float acc[4][4][4];
#pragma unroll
    for (int i = 0; i < 4; i++)
#pragma unroll
        for (int j = 0; j < 4; j++)
#pragma unroll
            for (int t = 0; t < 4; t++) acc[i][j][t] = 0.f;

    const __half* Ag = A + (size_t)(m0 + lrow) * lda + lcol;
    const __half* Bg = B + (size_t)(n0 + lrow) * ldb + lcol;
    const uint32_t asb = sptr(&As[0][0]);
    const uint32_t bsb = sptr(&Bs[0][0]);
    const uint32_t so  = 128 * 40 * 2;

    auto load_stage = [&](int st, int k0) {
        uint32_t a = asb + st * so, b2 = bsb + st * so;
        CPA(a + (lrow * 40 + lcol) * 2,        Ag + k0);
        CPA(a + ((lrow + 64) * 40 + lcol) * 2, Ag + (size_t)64 * lda + k0);
        CPA(b2 + (lrow * 40 + lcol) * 2,        Bg + k0);
        CPA(b2 + ((lrow + 64) * 40 + lcol) * 2, Bg + (size_t)64 * ldb + k0);
        CPC();
    };
    load_stage(0, 0);

    const uint32_t a_fb = ((wm + (lane & 15)) * 40 + (lane >> 4) * 8) * 2;
    const uint32_t b_fb = ((wn + (lane & 7)) * 40 + ((lane >> 3) & 1) * 8) * 2;

    const int niter = K / 32;
    int buf = 0;
    for (int it = 0; it < niter; ++it) {
        if (it + 1 < niter) { load_stage(buf ^ 1, (it + 1) * 32); CPW1(); }
        else                { CPW0(); }
        __syncthreads();

        const uint32_t ab = asb + buf * so + a_fb;
        const uint32_t bb = bsb + buf * so + b_fb;
#pragma unroll
        for (int ks = 0; ks < 2; ++ks) {
            uint32_t a[4][4], bfr[4][2];
#pragma unroll
            for (int mi = 0; mi < 4; mi++)
                ldmx4(a[mi], ab + (mi * 16 * 40 + ks * 16) * 2);
#pragma unroll
            for (int nj = 0; nj < 4; nj++)
                ldmx2(bfr[nj], bb + (nj * 8 * 40 + ks * 16) * 2);
#pragma unroll
            for (int mi = 0; mi < 4; mi++)
#pragma unroll
                for (int nj = 0; nj < 4; nj++)
                    mma16816(acc[mi][nj], a[mi], bfr[nj]);
        }
        __syncthreads();
        buf ^= 1;
    }

    const int g  = lane >> 2;
    const int tg = lane & 3;
#pragma unroll
    for (int mi = 0; mi < 4; mi++) {
#pragma unroll
        for (int nj = 0; nj < 4; nj++) {
            const int r0 = m0 + wm + mi * 16 + g;
            const int cc = n0 + wn + nj * 8 + 2 * tg;
            float* a4 = acc[mi][nj];
            if (HALF_OUT) {
                __half* C = (__half*)Cp;
                *(__half2*)&C[(size_t)r0 * ldc + cc]       = __floats2half2_rn(a4[0], a4[1]);
                *(__half2*)&C[(size_t)(r0 + 8) * ldc + cc] = __floats2half2_rn(a4[2], a4[3]);
            } else {
                float* C = (float*)Cp;
                float b0 = 0.f, b1 = 0.f;
                if (BIAS) { float2 bb = *(const float2*)&bias[cc]; b0 = bb.x; b1 = bb.y; }
                *(float2*)&C[(size_t)r0 * ldc + cc]       = make_float2(a4[0] + b0, a4[1] + b1);
                *(float2*)&C[(size_t)(r0 + 8) * ldc + cc] = make_float2(a4[2] + b0, a4[3] + b1);
            }
        }
    }
}

// 3. split-K q@k^T partials (fp32 out)
__global__ void __launch_bounds__(256) k_qk()
{
    const int bh = blockIdx.y;
    const __half* qb = g_qkv + ((size_t)(bh >> 2) * 1536 + (bh & 3) * DHn) * Nn
                     + blockIdx.x * 512;
    const __half* kb = qb + (size_t)512 * Nn;
    float* C = g_attnP + ((size_t)bh * QK_SPLIT + blockIdx.x) * (DHn * DHn);
    gemm_abt_f16<false, false>(qb, kb, C, nullptr, 512, Nn, Nn, DHn, 0, 0);
}

// 5. xca = v_t @ attn^T (half out, token-major)
__global__ void __launch_bounds__(256) k_av()
{
    const int bh = blockIdx.z;
    const int b = bh >> 2, h = bh & 3;
    const __half* A  = g_vt  + (size_t)b * Nn * Cn + h * DHn;
    const __half* Bt = g_attn + (size_t)bh * DHn * DHn;
    __half* C = g_xca + (size_t)b * Nn * Cn + h * DHn;
    gemm_abt_f16<true, false>(A, Bt, C, nullptr, 128, 512, 128, 512,
                              blockIdx.y * 128, 0);
}

// ---------------- small kernels ---------------------------------------------
__global__ void __launch_bounds__(256) f2h(const float* __restrict__ s,
                                           __half* __restrict__ d, int n4)
{
    const int i = blockIdx.x * 256 + threadIdx.x;
    if (i < n4) {
        float4 v = ((const float4*)s)[i];
        ((__half2*)d)[i * 2]     = __floats2half2_rn(v.x, v.y);
        ((__half2*)d)[i * 2 + 1] = __floats2half2_rn(v.z, v.w);
    }
}

__global__ void __launch_bounds__(256) norm_kernel()
{
    const int b = blockIdx.x >> 10;
    const int m = blockIdx.x & 1023;
    const __half2* row = (const __half2*)(g_qkv + ((size_t)b * 1536 + m) * Nn);
    float ss = 0.f;
    for (int i = threadIdx.x; i < Nn / 2; i += 256) {
        float2 f = __half22float2(row[i]);
        ss = fmaf(f.x, f.x, fmaf(f.y, f.y, ss));
    }
    __shared__ float red[256];
    red[threadIdx.x] = ss;
    __syncthreads();
    for (int off = 128; off; off >>= 1) {
        if (threadIdx.x < off) red[threadIdx.x] += red[threadIdx.x + off];
        __syncthreads();
    }
    if (threadIdx.x == 0)
        g_inv[b * 1024 + m] = 1.f / fmaxf(sqrtf(red[0]), 1e-12f);
}

__global__ void __launch_bounds__(256) vtrans()
{
    __shared__ __half ts[32][33];
    const int n0 = blockIdx.x * 32, hd0 = blockIdx.y * 32, b = blockIdx.z;
    const int tx = threadIdx.x, ty = threadIdx.y;
    const __half* src = g_qkv + ((size_t)b * 1536 + 1024 + hd0) * Nn + n0;
#pragma unroll
    for (int r = 0; r < 4; r++)
        ts[ty + r * 8][tx] = src[(size_t)(ty + r * 8) * Nn + tx];
    __syncthreads();
    __half* dst = g_vt + ((size_t)b * Nn + n0) * Cn + hd0;
#pragma unroll
    for (int r = 0; r < 4; r++)
        dst[(size_t)(ty + r * 8) * Cn + tx] = ts[tx][ty + r * 8];
}

__global__ void __launch_bounds__(128) softmax_kernel(const float* __restrict__ temp)
{
    const int bh = blockIdx.x >> 7;
    const int c  = blockIdx.x & 127;
    const int b  = bh >> 2, h = bh & 3;
    const int d  = threadIdx.x;

    const float* base = g_attnP + (size_t)bh * QK_SPLIT * (DHn * DHn) + c * DHn + d;
    float s = 0.f;
#pragma unroll
    for (int p = 0; p < QK_SPLIT; p++) s += base[(size_t)p * (DHn * DHn)];

    const float qinv = g_inv[b * 1024 + h * DHn + c];
    const float kinv = g_inv[b * 1024 + 512 + h * DHn + d];
    const float val  = s * qinv * kinv * temp[h];

    __shared__ float red[128];
    red[d] = val;
    __syncthreads();
    for (int off = 64; off; off >>= 1) {
        if (d < off) red[d] = fmaxf(red[d], red[d + off]);
        __syncthreads();
    }
    const float mx = red[0];
    __syncthreads();
    const float e = expf(val - mx);
    red[d] = e;
    __syncthreads();
    for (int off = 64; off; off >>= 1) {
        if (d < off) red[d] += red[d + off];
        __syncthreads();
    }
    g_attn[(size_t)bh * (DHn * DHn) + c * DHn + d] = __float2half_rn(e / red[0]);
}

// ---------------------------------------------------------------------------
extern "C" void kernel_launch(void* const* d_in, const int* in_sizes, int n_in,
                              void* d_out, int out_size)
{
    const float* x    = (const float*)d_in[0];
    const float* Wqkv = (const float*)d_in[1];
    const float* Wout = (const float*)d_in[2];
    const float* bout = (const float*)d_in[3];
    const float* temp = (const float*)d_in[4];
    float* out = (float*)d_out;

    __half *xh, *wqh, *woh;
    cudaGetSymbolAddress((void**)&xh,  g_xh);
    cudaGetSymbolAddress((void**)&wqh, g_wqh);
    cudaGetSymbolAddress((void**)&woh, g_woh);

    cudaFuncSetAttribute(k_qkv, cudaFuncAttributeMaxDynamicSharedMemorySize, BIG_SMEM);
    cudaFuncSetAttribute(k_out, cudaFuncAttributeMaxDynamicSharedMemorySize, BIG_SMEM);

    // 0. fp32 -> fp16 conversions
    f2h<<<(Bn * Nn * Cn / 4 + 255) / 256, 256>>>(x, xh, Bn * Nn * Cn / 4);
    f2h<<<(1536 * 512 / 4 + 255) / 256, 256>>>(Wqkv, wqh, 1536 * 512 / 4);
    f2h<<<(512 * 512 / 4 + 255) / 256, 256>>>(Wout, woh, 512 * 512 / 4);

    // 1. QKV GEMM (pipelined, 2 CTAs/SM), channel-major output
    k_qkv<<<dim3(64, 12, 4), 128, BIG_SMEM>>>();

    // 2. inverse L2 norms
    norm_kernel<<<Bn * 1024, 256>>>();

    // 2b. v transpose to token-major
    vtrans<<<dim3(Nn / 32, 16, Bn), dim3(32, 8)>>>();

    // 3. split-K q@k^T partials
    k_qk<<<dim3(QK_SPLIT, 16), 256>>>();

    // 4. reduce + scale + softmax
    softmax_kernel<<<16 * 128, 128>>>(temp);

    // 5. xca = attn @ v (token-major output)
    k_av<<<dim3(1, 64, 16), 256>>>();

    // 6. out = xca @ Wout^T + bias (pipelined, 2 CTAs/SM)
    k_out<<<dim3(4, 256), 128, BIG_SMEM>>>(out, bout);
}

// round 8
// speedup vs baseline: 1.3806x; 1.1260x over previous
#include <cuda_runtime.h>
#include <cuda_fp16.h>
#include <cstddef>
#include <cstdint>

#define Bn   4
#define Nn   8192
#define Cn   512
#define DHn  128
#define QK_SPLIT 16

// ---------------- scratch (device globals) ---------------------------------
__device__ __align__(128) __half g_xh  [(size_t)Bn * Nn * Cn];
__device__ __align__(128) __half g_wqh [1536 * 512];
__device__ __align__(128) __half g_woh [512 * 512];
__device__ __align__(128) __half g_qkv [(size_t)Bn * 1024 * Nn];   // q,k channel-major
__device__ __align__(128) __half g_vt  [(size_t)Bn * Nn * Cn];     // v token-major
__device__ __align__(128) float  g_nP  [Bn * 64 * 1024];           // norm partials
__device__ __align__(128) float  g_inv [Bn * 1024];
__device__ __align__(128) float  g_attnP[16 * QK_SPLIT * DHn * DHn];
__device__ __align__(128) __half g_attn [16 * DHn * DHn];
__device__ __align__(128) __half g_xca [(size_t)Bn * Nn * Cn];

// ---------------- PTX helpers ----------------------------------------------
__device__ __forceinline__ uint32_t sptr(const void* p) {
    return (uint32_t)__cvta_generic_to_shared(p);
}
#define CPA(dst, src) asm volatile("cp.async.cg.shared.global [%0],[%1],16;\n" \
                                   :: "r"(dst), "l"(src))
#define CPC() asm volatile("cp.async.commit_group;\n")
#define CPW0() asm volatile("cp.async.wait_group 0;\n")
#define CPW1() asm volatile("cp.async.wait_group 1;\n")

__device__ __forceinline__ void ldmx4(uint32_t* r, uint32_t a) {
    asm volatile("ldmatrix.sync.aligned.m8n8.x4.shared.b16 {%0,%1,%2,%3},[%4];"
                 : "=r"(r[0]), "=r"(r[1]), "=r"(r[2]), "=r"(r[3]) : "r"(a));
}
__device__ __forceinline__ void mma16816(float* c, const uint32_t* a, const uint32_t* b) {
    asm volatile(
        "mma.sync.aligned.m16n8k16.row.col.f32.f16.f16.f32 "
        "{%0,%1,%2,%3},{%4,%5,%6,%7},{%8,%9},{%0,%1,%2,%3};"
        : "+f"(c[0]), "+f"(c[1]), "+f"(c[2]), "+f"(c[3])
        : "r"(a[0]), "r"(a[1]), "r"(a[2]), "r"(a[3]), "r"(b[0]), "r"(b[1]));
}

// ---------------------------------------------------------------------------
// Shared mainloop macro pieces for the pipelined 128x128 GEMM (4 warps,
// 64x64 warp tiles, BK=32, 3-stage cp.async ring, fragment double buffer).
// ---------------------------------------------------------------------------
#define STAGE_BYTES (128 * 40 * 2 + 128 * 40 * 2)   // 20480
#define BIG_SMEM    (3 * STAGE_BYTES)               // 61440

// The mainloop computes acc[4][8][4] for A[m0..+128,:K] . B[n0..+128,:K]^T.
#define GEMM_MAINLOOP(A, B, K, lda, ldb, m0, n0)                               \
    const uint32_t s0 = sptr(dsm);                                             \
    const int tid  = threadIdx.x;                                              \
    const int lane = tid & 31;                                                 \
    const int wid  = tid >> 5;                                                 \
    const int wm   = (wid & 1) * 64;                                           \
    const int wn   = (wid >> 1) * 64;                                          \
    float acc[4][8][4];                                                        \
    _Pragma("unroll") for (int i = 0; i < 4; i++)                              \
    _Pragma("unroll") for (int j = 0; j < 8; j++)                              \
    _Pragma("unroll") for (int t = 0; t < 4; t++) acc[i][j][t] = 0.f;          \
    const int lrow = tid >> 2;                                                 \
    const int lc8  = (tid & 3) * 8;                                            \
    const __half* Ag = (A) + (size_t)((m0) + lrow) * (lda) + lc8;              \
    const __half* Bg = (B) + (size_t)((n0) + lrow) * (ldb) + lc8;              \
    auto load_stage = [&](int st, int k0) {                                    \
        const uint32_t a = s0 + st * STAGE_BYTES;                              \
        const uint32_t b = a + 128 * 40 * 2;                                   \
        _Pragma("unroll") for (int u = 0; u < 4; u++) {                        \
            CPA(a + ((lrow + u * 32) * 40 + lc8) * 2,                          \
                Ag + (size_t)(u * 32) * (lda) + k0);                           \
            CPA(b + ((lrow + u * 32) * 40 + lc8) * 2,                          \
                Bg + (size_t)(u * 32) * (ldb) + k0);                           \
        }                                                                      \
        CPC();                                                                 \
    };                                                                         \
    const uint32_t a_fb = ((wm + (lane & 15)) * 40 + (lane >> 4) * 8) * 2;     \
    const uint32_t b_fb = 128 * 40 * 2 +                                       \
        ((wn + (lane & 7) + (lane >> 4) * 8) * 40 + ((lane >> 3) & 1) * 8) * 2;\
    uint32_t af[2][4][4], bf[2][4][4];                                         \
    auto ldfrags = [&](int slot, int st, int ks) {                             \
        const uint32_t ab = s0 + st * STAGE_BYTES + a_fb + ks * 32;            \
        const uint32_t bb = s0 + st * STAGE_BYTES + b_fb + ks * 32;            \
        _Pragma("unroll") for (int mi = 0; mi < 4; mi++)                       \
            ldmx4(af[slot][mi], ab + mi * 16 * 80);                            \
        _Pragma("unroll") for (int nj = 0; nj < 4; nj++)                       \
            ldmx4(bf[slot][nj], bb + nj * 16 * 80);                            \
    };                                                                         \
    auto mma_all = [&](int slot) {                                             \
        _Pragma("unroll") for (int mi = 0; mi < 4; mi++)                       \
        _Pragma("unroll") for (int nj = 0; nj < 8; nj++)                       \
            mma16816(acc[mi][nj], af[slot][mi], &bf[slot][nj >> 1][(nj & 1) * 2]); \
    };                                                                         \
    const int niter = (K) / 32;                                                \
    load_stage(0, 0);                                                          \
    load_stage(1, 32);                                                         \
    CPW1();                                                                    \
    __syncthreads();                                                           \
    ldfrags(0, 0, 0);                                                          \
    int st = 0;                                                                \
    for (int it = 0; it < niter; ++it) {                                       \
        ldfrags(1, st, 1);                                                     \
        if (it + 2 < niter) load_stage((st + 2) % 3, (it + 2) * 32);           \
        mma_all(0);                                                            \
        if (it + 1 < niter) {                                                  \
            if (it + 2 < niter) { CPW1(); } else { CPW0(); }                   \
            __syncthreads();                                                   \
            const int nst = (st + 1 == 3) ? 0 : st + 1;                        \
            ldfrags(0, nst, 0);                                                \
            st = nst;                                                          \
        }                                                                      \
        mma_all(1);                                                            \
    }

// ---------------------------------------------------------------------------
// Generic pipelined GEMM with plain epilogue
// ---------------------------------------------------------------------------
template<bool HALF_OUT, bool BIAS>
__device__ __forceinline__ void gemm_big(
    const __half* __restrict__ A, const __half* __restrict__ B,
    void* __restrict__ Cp, const float* __restrict__ bias,
    int K, int lda, int ldb, int ldc, int m0, int n0)
{
    extern __shared__ char dsm[];
    GEMM_MAINLOOP(A, B, K, lda, ldb, m0, n0)

    const int g  = lane >> 2;
    const int tg = lane & 3;
#pragma unroll
    for (int mi = 0; mi < 4; mi++) {
#pragma unroll
        for (int nj = 0; nj < 8; nj++) {
            const int r0 = m0 + wm + mi * 16 + g;
            const int cc = n0 + wn + nj * 8 + 2 * tg;
            float* a4 = acc[mi][nj];
            if (HALF_OUT) {
                __half* C = (__half*)Cp;
                *(__half2*)&C[(size_t)r0 * ldc + cc]       = __floats2half2_rn(a4[0], a4[1]);
                *(__half2*)&C[(size_t)(r0 + 8) * ldc + cc] = __floats2half2_rn(a4[2], a4[3]);
            } else {
                float* C = (float*)Cp;
                float b0 = 0.f, b1 = 0.f;
                if (BIAS) { float2 bb = *(const float2*)&bias[cc]; b0 = bb.x; b1 = bb.y; }
                *(float2*)&C[(size_t)r0 * ldc + cc]       = make_float2(a4[0] + b0, a4[1] + b1);
                *(float2*)&C[(size_t)(r0 + 8) * ldc + cc] = make_float2(a4[2] + b0, a4[3] + b1);
            }
        }
    }
}

// ---------------------------------------------------------------------------
// k_qkv: qkv[b][m][n] = Wqkv[m,:] . x[b][n,:] with FUSED epilogues:
//  m<1024 (q,k): channel-major store + per-row sum-of-squares partials
//  m>=1024 (v) : transpose in smem, store token-major into g_vt
// grid (64 n-tiles, 12 m-tiles, 4 batches), 128 threads, 2 CTAs/SM.
// ---------------------------------------------------------------------------
__global__ void __launch_bounds__(128, 2) k_qkv()
{
    extern __shared__ char dsm[];
    const int m0 = blockIdx.y * 128;
    const int n0 = blockIdx.x * 128;
    const int b  = blockIdx.z;
    const __half* Bx = g_xh + (size_t)b * Nn * Cn;

    GEMM_MAINLOOP(g_wqh, Bx, 512, 512, 512, m0, n0)

    const int g  = lane >> 2;
    const int tg = lane & 3;

    if (m0 < 1024) {
        // ---- channel-major q/k store ----
        __half* C = g_qkv + (size_t)b * 1024 * Nn;
#pragma unroll
        for (int mi = 0; mi < 4; mi++) {
#pragma unroll
            for (int nj = 0; nj < 8; nj++) {
                const int r0 = m0 + wm + mi * 16 + g;
                const int cc = n0 + wn + nj * 8 + 2 * tg;
                float* a4 = acc[mi][nj];
                *(__half2*)&C[(size_t)r0 * Nn + cc]       = __floats2half2_rn(a4[0], a4[1]);
                *(__half2*)&C[(size_t)(r0 + 8) * Nn + cc] = __floats2half2_rn(a4[2], a4[3]);
            }
        }
        // ---- fused norm partials ----
        float* snorm = (float*)dsm;
        __syncthreads();               // stage smem no longer needed
        if (tid < 128) snorm[tid] = 0.f;
        __syncthreads();
#pragma unroll
        for (int mi = 0; mi < 4; mi++) {
            float ssA = 0.f, ssB = 0.f;
#pragma unroll
            for (int nj = 0; nj < 8; nj++) {
                float* a4 = acc[mi][nj];
                ssA = fmaf(a4[0], a4[0], fmaf(a4[1], a4[1], ssA));
                ssB = fmaf(a4[2], a4[2], fmaf(a4[3], a4[3], ssB));
            }
            ssA += __shfl_xor_sync(0xffffffffu, ssA, 1);
            ssA += __shfl_xor_sync(0xffffffffu, ssA, 2);
            ssB += __shfl_xor_sync(0xffffffffu, ssB, 1);
            ssB += __shfl_xor_sync(0xffffffffu, ssB, 2);
            if (tg == 0) {
                atomicAdd(&snorm[wm + mi * 16 + g], ssA);
                atomicAdd(&snorm[wm + mi * 16 + g + 8], ssB);
            }
        }
        __syncthreads();
        if (tid < 128)
            g_nP[((size_t)b * 64 + blockIdx.x) * 1024 + m0 + tid] = snorm[tid];
    } else {
        // ---- v: transpose to token-major ----
        __half* tS = (__half*)dsm;     // [128 n][136 m] halves
        __syncthreads();               // stage smem no longer needed
#pragma unroll
        for (int mi = 0; mi < 4; mi++) {
#pragma unroll
            for (int nj = 0; nj < 8; nj++) {
                const int ml = wm + mi * 16 + g;
                const int nl = wn + nj * 8 + 2 * tg;
                float* a4 = acc[mi][nj];
                tS[nl * 136 + ml]           = __float2half_rn(a4[0]);
                tS[(nl + 1) * 136 + ml]     = __float2half_rn(a4[1]);
                tS[nl * 136 + ml + 8]       = __float2half_rn(a4[2]);
                tS[(nl + 1) * 136 + ml + 8] = __float2half_rn(a4[3]);
            }
        }
        __syncthreads();
        const int hd0 = m0 - 1024;
#pragma unroll
        for (int p = 0; p < 4; p++) {
            const int nn = (tid >> 2) + p * 32;
            const int q  = tid & 3;
            const __half* src = tS + nn * 136 + q * 32;
            __half* dst = g_vt + ((size_t)b * Nn + n0 + nn) * Cn + hd0 + q * 32;
#pragma unroll
            for (int k = 0; k < 4; k++)
                ((uint4*)dst)[k] = ((const uint4*)src)[k];
        }
    }
}

// reduce norm partials -> inverse norms
__global__ void __launch_bounds__(256) inv_kernel()
{
    const int idx = blockIdx.x * 256 + threadIdx.x;   // 0..4095
    const int b = idx >> 10, m = idx & 1023;
    float s = 0.f;
#pragma unroll 8
    for (int j = 0; j < 64; j++)
        s += g_nP[((size_t)b * 64 + j) * 1024 + m];
    g_inv[b * 1024 + m] = 1.f / fmaxf(sqrtf(s), 1e-12f);
}

// 3. split-K q@k^T partials (fp32 out)
__global__ void __launch_bounds__(128, 2) k_qk()
{
    const int bh = blockIdx.y;
    const __half* qb = g_qkv + ((size_t)(bh >> 2) * 1024 + (bh & 3) * DHn) * Nn
                     + blockIdx.x * 512;
    const __half* kb = qb + (size_t)512 * Nn;
    float* C = g_attnP + ((size_t)bh * QK_SPLIT + blockIdx.x) * (DHn * DHn);
    gemm_big<false, false>(qb, kb, C, nullptr, 512, Nn, Nn, DHn, 0, 0);
}

// 5. xca = v_t @ attn^T (half out, token-major)
__global__ void __launch_bounds__(128, 2) k_av()
{
    const int bh = blockIdx.z;
    const int b = bh >> 2, h = bh & 3;
    const __half* A  = g_vt  + (size_t)b * Nn * Cn + h * DHn;
    const __half* Bt = g_attn + (size_t)bh * DHn * DHn;
    __half* C = g_xca + (size_t)b * Nn * Cn + h * DHn;
    gemm_big<true, false>(A, Bt, C, nullptr, 128, 512, 128, 512,
                          blockIdx.y * 128, 0);
}

// 6. out = xca @ Wout^T + bias   (fp32 out)
__global__ void __launch_bounds__(128, 2) k_out(float* __restrict__ out,
                                                const float* __restrict__ bias)
{
    gemm_big<false, true>(g_xca, g_woh, out, bias, 512, 512, 512, 512,
                          blockIdx.y * 128, blockIdx.x * 128);
}

// ---------------- small kernels ---------------------------------------------
__global__ void __launch_bounds__(256) f2h(const float* __restrict__ s,
                                           __half* __restrict__ d, int n4)
{
    const int i = blockIdx.x * 256 + threadIdx.x;
    if (i < n4) {
        float4 v = ((const float4*)s)[i];
        ((__half2*)d)[i * 2]     = __floats2half2_rn(v.x, v.y);
        ((__half2*)d)[i * 2 + 1] = __floats2half2_rn(v.z, v.w);
    }
}

__global__ void __launch_bounds__(128) softmax_kernel(const float* __restrict__ temp)
{
    const int bh = blockIdx.x >> 7;
    const int c  = blockIdx.x & 127;
    const int b  = bh >> 2, h = bh & 3;
    const int d  = threadIdx.x;

    const float* base = g_attnP + (size_t)bh * QK_SPLIT * (DHn * DHn) + c * DHn + d;
    float s = 0.f;
#pragma unroll
    for (int p = 0; p < QK_SPLIT; p++) s += base[(size_t)p * (DHn * DHn)];

    const float qinv = g_inv[b * 1024 + h * DHn + c];
    const float kinv = g_inv[b * 1024 + 512 + h * DHn + d];
    const float val  = s * qinv * kinv * temp[h];

    __shared__ float red[128];
    red[d] = val;
    __syncthreads();
    for (int off = 64; off; off >>= 1) {
        if (d < off) red[d] = fmaxf(red[d], red[d + off]);
        __syncthreads();
    }
    const float mx = red[0];
    __syncthreads();
    const float e = expf(val - mx);
    red[d] = e;
    __syncthreads();
    for (int off = 64; off; off >>= 1) {
        if (d < off) red[d] += red[d + off];
        __syncthreads();
    }
    g_attn[(size_t)bh * (DHn * DHn) + c * DHn + d] = __float2half_rn(e / red[0]);
}

// ---------------------------------------------------------------------------
extern "C" void kernel_launch(void* const* d_in, const int* in_sizes, int n_in,
                              void* d_out, int out_size)
{
    const float* x    = (const float*)d_in[0];
    const float* Wqkv = (const float*)d_in[1];
    const float* Wout = (const float*)d_in[2];
    const float* bout = (const float*)d_in[3];
    const float* temp = (const float*)d_in[4];
    float* out = (float*)d_out;

    __half *xh, *wqh, *woh;
    cudaGetSymbolAddress((void**)&xh,  g_xh);
    cudaGetSymbolAddress((void**)&wqh, g_wqh);
    cudaGetSymbolAddress((void**)&woh, g_woh);

    cudaFuncSetAttribute(k_qkv, cudaFuncAttributeMaxDynamicSharedMemorySize, BIG_SMEM);
    cudaFuncSetAttribute(k_qk,  cudaFuncAttributeMaxDynamicSharedMemorySize, BIG_SMEM);
    cudaFuncSetAttribute(k_av,  cudaFuncAttributeMaxDynamicSharedMemorySize, BIG_SMEM);
    cudaFuncSetAttribute(k_out, cudaFuncAttributeMaxDynamicSharedMemorySize, BIG_SMEM);

    // 0. fp32 -> fp16 conversions
    f2h<<<(Bn * Nn * Cn / 4 + 255) / 256, 256>>>(x, xh, Bn * Nn * Cn / 4);
    f2h<<<(1536 * 512 / 4 + 255) / 256, 256>>>(Wqkv, wqh, 1536 * 512 / 4);
    f2h<<<(512 * 512 / 4 + 255) / 256, 256>>>(Wout, woh, 512 * 512 / 4);

    // 1. QKV GEMM with fused norm partials + v transpose
    k_qkv<<<dim3(64, 12, 4), 128, BIG_SMEM>>>();

    // 2. inverse L2 norms (reduce partials)
    inv_kernel<<<16, 256>>>();

    // 3. split-K q@k^T partials
    k_qk<<<dim3(QK_SPLIT, 16), 128, BIG_SMEM>>>();

    // 4. reduce + scale + softmax
    softmax_kernel<<<16 * 128, 128>>>(temp);

    // 5. xca = attn @ v (token-major output)
    k_av<<<dim3(1, 64, 16), 128, BIG_SMEM>>>();

    // 6. out = xca @ Wout^T + bias
    k_out<<<dim3(4, 256), 128, BIG_SMEM>>>(out, bout);
}

// round 9
// speedup vs baseline: 1.4651x; 1.0612x over previous
#include <cuda_runtime.h>
#include <cuda_fp16.h>
#include <cstddef>
#include <cstdint>

#define Bn   4
#define Nn   8192
#define Cn   512
#define DHn  128
#define QK_SPLIT 16

// ---------------- scratch (device globals) ---------------------------------
__device__ __align__(128) __half g_xh  [(size_t)Bn * Nn * Cn];
__device__ __align__(128) __half g_wqh [1536 * 512];
__device__ __align__(128) __half g_woh [512 * 512];
__device__ __align__(128) __half g_qkv [(size_t)Bn * 1024 * Nn];   // q,k channel-major
__device__ __align__(128) __half g_vt  [(size_t)Bn * Nn * Cn];     // v token-major
__device__ __align__(128) float  g_nP  [Bn * 64 * 1024];           // norm partials
__device__ __align__(128) float  g_inv [Bn * 1024];
__device__ __align__(128) float  g_attnP[16 * QK_SPLIT * DHn * DHn];
__device__ __align__(128) __half g_attnT[16 * DHn * DHn];          // [bh][d][c]
__device__ __align__(128) __half g_M   [Bn * Cn * Cn];             // fused Wout@attn

// ---------------- PTX helpers ----------------------------------------------
__device__ __forceinline__ uint32_t sptr(const void* p) {
    return (uint32_t)__cvta_generic_to_shared(p);
}
#define CPA(dst, src) asm volatile("cp.async.cg.shared.global [%0],[%1],16;\n" \
                                   :: "r"(dst), "l"(src))
#define CPC() asm volatile("cp.async.commit_group;\n")
#define CPW0() asm volatile("cp.async.wait_group 0;\n")
#define CPW1() asm volatile("cp.async.wait_group 1;\n")

__device__ __forceinline__ void ldmx4(uint32_t* r, uint32_t a) {
    asm volatile("ldmatrix.sync.aligned.m8n8.x4.shared.b16 {%0,%1,%2,%3},[%4];"
                 : "=r"(r[0]), "=r"(r[1]), "=r"(r[2]), "=r"(r[3]) : "r"(a));
}
__device__ __forceinline__ void mma16816(float* c, const uint32_t* a, const uint32_t* b) {
    asm volatile(
        "mma.sync.aligned.m16n8k16.row.col.f32.f16.f16.f32 "
        "{%0,%1,%2,%3},{%4,%5,%6,%7},{%8,%9},{%0,%1,%2,%3};"
        : "+f"(c[0]), "+f"(c[1]), "+f"(c[2]), "+f"(c[3])
        : "r"(a[0]), "r"(a[1]), "r"(a[2]), "r"(a[3]), "r"(b[0]), "r"(b[1]));
}

// ---------------------------------------------------------------------------
// Pipelined 128x128 GEMM mainloop (4 warps, 64x64 warp tiles, BK=32,
// 3-stage cp.async ring, fragment double buffer).
// ---------------------------------------------------------------------------
#define STAGE_BYTES (128 * 40 * 2 + 128 * 40 * 2)   // 20480
#define BIG_SMEM    (3 * STAGE_BYTES)               // 61440

#define GEMM_MAINLOOP(A, B, K, lda, ldb, m0, n0)                               \
    const uint32_t s0 = sptr(dsm);                                             \
    const int tid  = threadIdx.x;                                              \
    const int lane = tid & 31;                                                 \
    const int wid  = tid >> 5;                                                 \
    const int wm   = (wid & 1) * 64;                                           \
    const int wn   = (wid >> 1) * 64;                                          \
    float acc[4][8][4];                                                        \
    _Pragma("unroll") for (int i = 0; i < 4; i++)                              \
    _Pragma("unroll") for (int j = 0; j < 8; j++)                              \
    _Pragma("unroll") for (int t = 0; t < 4; t++) acc[i][j][t] = 0.f;          \
    const int lrow = tid >> 2;                                                 \
    const int lc8  = (tid & 3) * 8;                                            \
    const __half* Ag = (A) + (size_t)((m0) + lrow) * (lda) + lc8;              \
    const __half* Bg = (B) + (size_t)((n0) + lrow) * (ldb) + lc8;              \
    auto load_stage = [&](int st, int k0) {                                    \
        const uint32_t a = s0 + st * STAGE_BYTES;                              \
        const uint32_t b = a + 128 * 40 * 2;                                   \
        _Pragma("unroll") for (int u = 0; u < 4; u++) {                        \
            CPA(a + ((lrow + u * 32) * 40 + lc8) * 2,                          \
                Ag + (size_t)(u * 32) * (lda) + k0);                           \
            CPA(b + ((lrow + u * 32) * 40 + lc8) * 2,                          \
                Bg + (size_t)(u * 32) * (ldb) + k0);                           \
        }                                                                      \
        CPC();                                                                 \
    };                                                                         \
    const uint32_t a_fb = ((wm + (lane & 15)) * 40 + (lane >> 4) * 8) * 2;     \
    const uint32_t b_fb = 128 * 40 * 2 +                                       \
        ((wn + (lane & 7) + (lane >> 4) * 8) * 40 + ((lane >> 3) & 1) * 8) * 2;\
    uint32_t af[2][4][4], bf[2][4][4];                                         \
    auto ldfrags = [&](int slot, int st, int ks) {                             \
        const uint32_t ab = s0 + st * STAGE_BYTES + a_fb + ks * 32;            \
        const uint32_t bb = s0 + st * STAGE_BYTES + b_fb + ks * 32;            \
        _Pragma("unroll") for (int mi = 0; mi < 4; mi++)                       \
            ldmx4(af[slot][mi], ab + mi * 16 * 80);                            \
        _Pragma("unroll") for (int nj = 0; nj < 4; nj++)                       \
            ldmx4(bf[slot][nj], bb + nj * 16 * 80);                            \
    };                                                                         \
    auto mma_all = [&](int slot) {                                             \
        _Pragma("unroll") for (int mi = 0; mi < 4; mi++)                       \
        _Pragma("unroll") for (int nj = 0; nj < 8; nj++)                       \
            mma16816(acc[mi][nj], af[slot][mi], &bf[slot][nj >> 1][(nj & 1) * 2]); \
    };                                                                         \
    const int niter = (K) / 32;                                                \
    load_stage(0, 0);                                                          \
    load_stage(1, 32);                                                         \
    CPW1();                                                                    \
    __syncthreads();                                                           \
    ldfrags(0, 0, 0);                                                          \
    int st = 0;                                                                \
    for (int it = 0; it < niter; ++it) {                                       \
        ldfrags(1, st, 1);                                                     \
        if (it + 2 < niter) load_stage((st + 2) % 3, (it + 2) * 32);           \
        mma_all(0);                                                            \
        if (it + 1 < niter) {                                                  \
            if (it + 2 < niter) { CPW1(); } else { CPW0(); }                   \
            __syncthreads();                                                   \
            const int nst = (st + 1 == 3) ? 0 : st + 1;                        \
            ldfrags(0, nst, 0);                                                \
            st = nst;                                                          \
        }                                                                      \
        mma_all(1);                                                            \
    }

// ---------------------------------------------------------------------------
// Generic pipelined GEMM with plain epilogue
// ---------------------------------------------------------------------------
template<bool HALF_OUT, bool BIAS>
__device__ __forceinline__ void gemm_big(
    const __half* __restrict__ A, const __half* __restrict__ B,
    void* __restrict__ Cp, const float* __restrict__ bias,
    int K, int lda, int ldb, int ldc, int m0, int n0)
{
    extern __shared__ char dsm[];
    GEMM_MAINLOOP(A, B, K, lda, ldb, m0, n0)

    const int g  = lane >> 2;
    const int tg = lane & 3;
#pragma unroll
    for (int mi = 0; mi < 4; mi++) {
#pragma unroll
        for (int nj = 0; nj < 8; nj++) {
            const int r0 = m0 + wm + mi * 16 + g;
            const int cc = n0 + wn + nj * 8 + 2 * tg;
            float* a4 = acc[mi][nj];
            if (HALF_OUT) {
                __half* C = (__half*)Cp;
                *(__half2*)&C[(size_t)r0 * ldc + cc]       = __floats2half2_rn(a4[0], a4[1]);
                *(__half2*)&C[(size_t)(r0 + 8) * ldc + cc] = __floats2half2_rn(a4[2], a4[3]);
            } else {
                float* C = (float*)Cp;
                float b0 = 0.f, b1 = 0.f;
                if (BIAS) { float2 bb = *(const float2*)&bias[cc]; b0 = bb.x; b1 = bb.y; }
                *(float2*)&C[(size_t)r0 * ldc + cc]       = make_float2(a4[0] + b0, a4[1] + b1);
                *(float2*)&C[(size_t)(r0 + 8) * ldc + cc] = make_float2(a4[2] + b0, a4[3] + b1);
            }
        }
    }
}

// ---------------------------------------------------------------------------
// k_qkv: qkv[b][m][n] = Wqkv[m,:] . x[b][n,:] with FUSED epilogues:
//  m<1024 (q,k): channel-major store + per-row sum-of-squares partials
//  m>=1024 (v) : transpose in smem, store token-major into g_vt
// ---------------------------------------------------------------------------
__global__ void __launch_bounds__(128, 2) k_qkv()
{
    extern __shared__ char dsm[];
    const int m0 = blockIdx.y * 128;
    const int n0 = blockIdx.x * 128;
    const int b  = blockIdx.z;
    const __half* Bx = g_xh + (size_t)b * Nn * Cn;

    GEMM_MAINLOOP(g_wqh, Bx, 512, 512, 512, m0, n0)

    const int g  = lane >> 2;
    const int tg = lane & 3;

    if (m0 < 1024) {
        __half* C = g_qkv + (size_t)b * 1024 * Nn;
#pragma unroll
        for (int mi = 0; mi < 4; mi++) {
#pragma unroll
            for (int nj = 0; nj < 8; nj++) {
                const int r0 = m0 + wm + mi * 16 + g;
                const int cc = n0 + wn + nj * 8 + 2 * tg;
                float* a4 = acc[mi][nj];
                *(__half2*)&C[(size_t)r0 * Nn + cc]       = __floats2half2_rn(a4[0], a4[1]);
                *(__half2*)&C[(size_t)(r0 + 8) * Nn + cc] = __floats2half2_rn(a4[2], a4[3]);
            }
        }
        float* snorm = (float*)dsm;
        __syncthreads();
        if (tid < 128) snorm[tid] = 0.f;
        __syncthreads();
#pragma unroll
        for (int mi = 0; mi < 4; mi++) {
            float ssA = 0.f, ssB = 0.f;
#pragma unroll
            for (int nj = 0; nj < 8; nj++) {
                float* a4 = acc[mi][nj];
                ssA = fmaf(a4[0], a4[0], fmaf(a4[1], a4[1], ssA));
                ssB = fmaf(a4[2], a4[2], fmaf(a4[3], a4[3], ssB));
            }
            ssA += __shfl_xor_sync(0xffffffffu, ssA, 1);
            ssA += __shfl_xor_sync(0xffffffffu, ssA, 2);
            ssB += __shfl_xor_sync(0xffffffffu, ssB, 1);
            ssB += __shfl_xor_sync(0xffffffffu, ssB, 2);
            if (tg == 0) {
                atomicAdd(&snorm[wm + mi * 16 + g], ssA);
                atomicAdd(&snorm[wm + mi * 16 + g + 8], ssB);
            }
        }
        __syncthreads();
        if (tid < 128)
            g_nP[((size_t)b * 64 + blockIdx.x) * 1024 + m0 + tid] = snorm[tid];
    } else {
        __half* tS = (__half*)dsm;     // [128 n][136 m]
        __syncthreads();
#pragma unroll
        for (int mi = 0; mi < 4; mi++) {
#pragma unroll
            for (int nj = 0; nj < 8; nj++) {
                const int ml = wm + mi * 16 + g;
                const int nl = wn + nj * 8 + 2 * tg;
                float* a4 = acc[mi][nj];
                tS[nl * 136 + ml]           = __float2half_rn(a4[0]);
                tS[(nl + 1) * 136 + ml]     = __float2half_rn(a4[1]);
                tS[nl * 136 + ml + 8]       = __float2half_rn(a4[2]);
                tS[(nl + 1) * 136 + ml + 8] = __float2half_rn(a4[3]);
            }
        }
        __syncthreads();
        const int hd0 = m0 - 1024;
#pragma unroll
        for (int p = 0; p < 4; p++) {
            const int nn = (tid >> 2) + p * 32;
            const int q  = tid & 3;
            const __half* src = tS + nn * 136 + q * 32;
            __half* dst = g_vt + ((size_t)b * Nn + n0 + nn) * Cn + hd0 + q * 32;
#pragma unroll
            for (int k = 0; k < 4; k++)
                ((uint4*)dst)[k] = ((const uint4*)src)[k];
        }
    }
}

// reduce norm partials -> inverse norms
__global__ void __launch_bounds__(256) inv_kernel()
{
    const int idx = blockIdx.x * 256 + threadIdx.x;
    const int b = idx >> 10, m = idx & 1023;
    float s = 0.f;
#pragma unroll 8
    for (int j = 0; j < 64; j++)
        s += g_nP[((size_t)b * 64 + j) * 1024 + m];
    g_inv[b * 1024 + m] = 1.f / fmaxf(sqrtf(s), 1e-12f);
}

// 3. split-K q@k^T partials (fp32 out)
__global__ void __launch_bounds__(128, 2) k_qk()
{
    const int bh = blockIdx.y;
    const __half* qb = g_qkv + ((size_t)(bh >> 2) * 1024 + (bh & 3) * DHn) * Nn
                     + blockIdx.x * 512;
    const __half* kb = qb + (size_t)512 * Nn;
    float* C = g_attnP + ((size_t)bh * QK_SPLIT + blockIdx.x) * (DHn * DHn);
    gemm_big<false, false>(qb, kb, C, nullptr, 512, Nn, Nn, DHn, 0, 0);
}

// 4. reduce + scale + softmax; writes TRANSPOSED attn: g_attnT[bh][d][c]
__global__ void __launch_bounds__(128) softmax_kernel(const float* __restrict__ temp)
{
    const int bh = blockIdx.x >> 7;
    const int c  = blockIdx.x & 127;
    const int b  = bh >> 2, h = bh & 3;
    const int d  = threadIdx.x;

    const float* base = g_attnP + (size_t)bh * QK_SPLIT * (DHn * DHn) + c * DHn + d;
    float s = 0.f;
#pragma unroll
    for (int p = 0; p < QK_SPLIT; p++) s += base[(size_t)p * (DHn * DHn)];

    const float qinv = g_inv[b * 1024 + h * DHn + c];
    const float kinv = g_inv[b * 1024 + 512 + h * DHn + d];
    const float val  = s * qinv * kinv * temp[h];

    __shared__ float red[128];
    red[d] = val;
    __syncthreads();
    for (int off = 64; off; off >>= 1) {
        if (d < off) red[d] = fmaxf(red[d], red[d + off]);
        __syncthreads();
    }
    const float mx = red[0];
    __syncthreads();
    const float e = expf(val - mx);
    red[d] = e;
    __syncthreads();
    for (int off = 64; off; off >>= 1) {
        if (d < off) red[d] += red[d + off];
        __syncthreads();
    }
    g_attnT[(size_t)bh * (DHn * DHn) + d * DHn + c] = __float2half_rn(e / red[0]);
}

// 5. M_b[j][h*128+d] = sum_c Wout[j][h*128+c] * attn_bh[c][d]   (half out)
//    A = Woh rows j (lda 512, offset h*128), B = attnT rows d (ldb 128).
//    grid (1, 4 j-tiles, 16 bh)
__global__ void __launch_bounds__(128, 2) k_M()
{
    const int bh = blockIdx.z;
    const int b = bh >> 2, h = bh & 3;
    const __half* A  = g_woh + h * DHn;
    const __half* Bt = g_attnT + (size_t)bh * DHn * DHn;
    __half* C = g_M + (size_t)b * Cn * Cn + h * DHn;
    gemm_big<true, false>(A, Bt, C, nullptr, DHn, 512, DHn, Cn,
                          blockIdx.y * 128, 0);
}

// 6. out[b] = v_t[b] @ M_b^T + bias   (fp32 out)
//    grid (4 j-tiles, 64 n-tiles, 4 batches)
__global__ void __launch_bounds__(128, 2) k_out(float* __restrict__ out,
                                                const float* __restrict__ bias)
{
    const int b = blockIdx.z;
    const __half* A = g_vt + (size_t)b * Nn * Cn;
    const __half* Bm = g_M + (size_t)b * Cn * Cn;
    float* C = out + (size_t)b * Nn * Cn;
    gemm_big<false, true>(A, Bm, C, bias, 512, 512, 512, 512,
                          blockIdx.y * 128, blockIdx.x * 128);
}

// ---------------- small kernels ---------------------------------------------
__global__ void __launch_bounds__(256) f2h(const float* __restrict__ s,
                                           __half* __restrict__ d, int n4)
{
    const int i = blockIdx.x * 256 + threadIdx.x;
    if (i < n4) {
        float4 v = ((const float4*)s)[i];
        ((__half2*)d)[i * 2]     = __floats2half2_rn(v.x, v.y);
        ((__half2*)d)[i * 2 + 1] = __floats2half2_rn(v.z, v.w);
    }
}

// ---------------------------------------------------------------------------
extern "C" void kernel_launch(void* const* d_in, const int* in_sizes, int n_in,
                              void* d_out, int out_size)
{
    const float* x    = (const float*)d_in[0];
    const float* Wqkv = (const float*)d_in[1];
    const float* Wout = (const float*)d_in[2];
    const float* bout = (const float*)d_in[3];
    const float* temp = (const float*)d_in[4];
    float* out = (float*)d_out;

    __half *xh, *wqh, *woh;
    cudaGetSymbolAddress((void**)&xh,  g_xh);
    cudaGetSymbolAddress((void**)&wqh, g_wqh);
    cudaGetSymbolAddress((void**)&woh, g_woh);

    cudaFuncSetAttribute(k_qkv, cudaFuncAttributeMaxDynamicSharedMemorySize, BIG_SMEM);
    cudaFuncSetAttribute(k_qk,  cudaFuncAttributeMaxDynamicSharedMemorySize, BIG_SMEM);
    cudaFuncSetAttribute(k_M,   cudaFuncAttributeMaxDynamicSharedMemorySize, BIG_SMEM);
    cudaFuncSetAttribute(k_out, cudaFuncAttributeMaxDynamicSharedMemorySize, BIG_SMEM);

    // 0. fp32 -> fp16 conversions
    f2h<<<(Bn * Nn * Cn / 4 + 255) / 256, 256>>>(x, xh, Bn * Nn * Cn / 4);
    f2h<<<(1536 * 512 / 4 + 255) / 256, 256>>>(Wqkv, wqh, 1536 * 512 / 4);
    f2h<<<(512 * 512 / 4 + 255) / 256, 256>>>(Wout, woh, 512 * 512 / 4);

    // 1. QKV GEMM with fused norm partials + v transpose
    k_qkv<<<dim3(64, 12, 4), 128, BIG_SMEM>>>();

    // 2. inverse L2 norms
    inv_kernel<<<16, 256>>>();

    // 3. split-K q@k^T partials
    k_qk<<<dim3(QK_SPLIT, 16), 128, BIG_SMEM>>>();

    // 4. reduce + scale + softmax (transposed output)
    softmax_kernel<<<16 * 128, 128>>>(temp);

    // 5. M = Wout_h @ attn_h  (tiny fused GEMM)
    k_M<<<dim3(1, 4, 16), 128, BIG_SMEM>>>();

    // 6. out = v_t @ M^T + bias
    k_out<<<dim3(4, 64, 4), 128, BIG_SMEM>>>(out, bout);
}

// round 10
// speedup vs baseline: 1.5140x; 1.0334x over previous
#include <cuda_runtime.h>
#include <cuda_fp16.h>
#include <cstddef>
#include <cstdint>

#define Bn   4
#define Nn   8192
#define Cn   512
#define DHn  128
#define QK_SPLIT 16

// ---------------- scratch (device globals) ---------------------------------
__device__ __align__(128) __half g_xh  [(size_t)Bn * Nn * Cn];
__device__ __align__(128) __half g_wqh [1536 * 512];
__device__ __align__(128) __half g_woh [512 * 512];
__device__ __align__(128) __half g_qkv [(size_t)Bn * 1024 * Nn];   // q,k channel-major
__device__ __align__(128) __half g_vt  [(size_t)Bn * Nn * Cn];     // v token-major
__device__ __align__(128) float  g_nP  [Bn * 64 * 1024];           // norm partials
__device__ __align__(128) float  g_inv [Bn * 1024];
__device__ __align__(128) float  g_attnP[16 * QK_SPLIT * DHn * DHn];
__device__ __align__(128) __half g_attnT[16 * DHn * DHn];          // [bh][d][c]
__device__ __align__(128) __half g_M   [Bn * Cn * Cn];             // fused Wout@attn

// ---------------- PTX helpers ----------------------------------------------
__device__ __forceinline__ uint32_t sptr(const void* p) {
    return (uint32_t)__cvta_generic_to_shared(p);
}
#define CPA(dst, src) asm volatile("cp.async.cg.shared.global [%0],[%1],16;\n" \
                                   :: "r"(dst), "l"(src))
#define CPC() asm volatile("cp.async.commit_group;\n")
#define CPW0() asm volatile("cp.async.wait_group 0;\n")
#define CPW1() asm volatile("cp.async.wait_group 1;\n")

__device__ __forceinline__ void ldmx4(uint32_t* r, uint32_t a) {
    asm volatile("ldmatrix.sync.aligned.m8n8.x4.shared.b16 {%0,%1,%2,%3},[%4];"
                 : "=r"(r[0]), "=r"(r[1]), "=r"(r[2]), "=r"(r[3]) : "r"(a));
}
__device__ __forceinline__ void mma16816(float* c, const uint32_t* a, const uint32_t* b) {
    asm volatile(
        "mma.sync.aligned.m16n8k16.row.col.f32.f16.f16.f32 "
        "{%0,%1,%2,%3},{%4,%5,%6,%7},{%8,%9},{%0,%1,%2,%3};"
        : "+f"(c[0]), "+f"(c[1]), "+f"(c[2]), "+f"(c[3])
        : "r"(a[0]), "r"(a[1]), "r"(a[2]), "r"(a[3]), "r"(b[0]), "r"(b[1]));
}

// ---------------------------------------------------------------------------
// Pipelined 128x128 GEMM mainloop, BK=64, 2-stage ring, ONE barrier per iter.
// 4 warps, 64x64 warp tiles, fragment slots ping-pong across 4 K-phases.
// Stage layout: A 128 rows x 144B (64 halves + 8 pad), B same at +18432.
// Requires K % 64 == 0 and K/64 >= 2.
// ---------------------------------------------------------------------------
#define STAGE_BYTES 36864
#define BIG_SMEM    (2 * STAGE_BYTES)   // 73728

#define GEMM_MAINLOOP(A, B, K, lda, ldb, m0, n0)                               \
    const uint32_t s0 = sptr(dsm);                                             \
    const int tid  = threadIdx.x;                                              \
    const int lane = tid & 31;                                                 \
    const int wid  = tid >> 5;                                                 \
    const int wm   = (wid & 1) * 64;                                           \
    const int wn   = (wid >> 1) * 64;                                          \
    float acc[4][8][4];                                                        \
    _Pragma("unroll") for (int i = 0; i < 4; i++)                              \
    _Pragma("unroll") for (int j = 0; j < 8; j++)                              \
    _Pragma("unroll") for (int t = 0; t < 4; t++) acc[i][j][t] = 0.f;          \
    const int lrow = tid >> 3;           /* 0..15 */                           \
    const int lc16 = tid & 7;                                                  \
    const __half* Ag = (A) + (size_t)((m0) + lrow) * (lda) + lc16 * 8;         \
    const __half* Bg = (B) + (size_t)((n0) + lrow) * (ldb) + lc16 * 8;         \
    auto load_stage = [&](int stg, int k0) {                                   \
        const uint32_t ad = s0 + stg * STAGE_BYTES + lrow * 144 + lc16 * 16;   \
        const uint32_t bd = ad + 18432;                                        \
        _Pragma("unroll") for (int u = 0; u < 8; u++) {                        \
            CPA(ad + u * (16 * 144), Ag + (size_t)(u * 16) * (lda) + k0);      \
            CPA(bd + u * (16 * 144), Bg + (size_t)(u * 16) * (ldb) + k0);      \
        }                                                                      \
        CPC();                                                                 \
    };                                                                         \
    const uint32_t a_fb = (wm + (lane & 15)) * 144 + (lane >> 4) * 16;         \
    const uint32_t b_fb = 18432 +                                              \
        (wn + (lane & 7) + ((lane >> 4) * 8)) * 144 + ((lane >> 3) & 1) * 16;  \
    uint32_t af[2][4][4], bf[2][4][4];                                         \
    auto ldfrags = [&](int slot, int stg, int ks) {                            \
        const uint32_t ab = s0 + stg * STAGE_BYTES + a_fb + ks * 32;           \
        const uint32_t bb = s0 + stg * STAGE_BYTES + b_fb + ks * 32;           \
        _Pragma("unroll") for (int mi = 0; mi < 4; mi++)                       \
            ldmx4(af[slot][mi], ab + mi * (16 * 144));                         \
        _Pragma("unroll") for (int nj = 0; nj < 4; nj++)                       \
            ldmx4(bf[slot][nj], bb + nj * (16 * 144));                         \
    };                                                                         \
    auto mma_all = [&](int slot) {                                             \
        _Pragma("unroll") for (int mi = 0; mi < 4; mi++)                       \
        _Pragma("unroll") for (int nj = 0; nj < 8; nj++)                       \
            mma16816(acc[mi][nj], af[slot][mi], &bf[slot][nj >> 1][(nj & 1) * 2]); \
    };                                                                         \
    const int niter = (K) / 64;                                                \
    load_stage(0, 0);                                                          \
    load_stage(1, 64);                                                         \
    CPW1();                                                                    \
    __syncthreads();                                                           \
    ldfrags(0, 0, 0);                                                          \
    int st = 0;                                                                \
    for (int it = 0; it < niter; ++it) {                                       \
        ldfrags(1, st, 1); mma_all(0);                                         \
        ldfrags(0, st, 2); mma_all(1);                                         \
        ldfrags(1, st, 3); mma_all(0);                                         \
        if (it + 1 < niter) {                                                  \
            CPW0();                                                            \
            __syncthreads();                                                   \
            if (it + 2 < niter) load_stage(st, (it + 2) * 64);                 \
            ldfrags(0, st ^ 1, 0);                                             \
            st ^= 1;                                                           \
        }                                                                      \
        mma_all(1);                                                            \
    }

// ---------------------------------------------------------------------------
// Generic pipelined GEMM with plain epilogue
// ---------------------------------------------------------------------------
template<bool HALF_OUT, bool BIAS>
__device__ __forceinline__ void gemm_big(
    const __half* __restrict__ A, const __half* __restrict__ B,
    void* __restrict__ Cp, const float* __restrict__ bias,
    int K, int lda, int ldb, int ldc, int m0, int n0)
{
    extern __shared__ char dsm[];
    GEMM_MAINLOOP(A, B, K, lda, ldb, m0, n0)

    const int g  = lane >> 2;
    const int tg = lane & 3;
#pragma unroll
    for (int mi = 0; mi < 4; mi++) {
#pragma unroll
        for (int nj = 0; nj < 8; nj++) {
            const int r0 = m0 + wm + mi * 16 + g;
            const int cc = n0 + wn + nj * 8 + 2 * tg;
            float* a4 = acc[mi][nj];
            if (HALF_OUT) {
                __half* C = (__half*)Cp;
                *(__half2*)&C[(size_t)r0 * ldc + cc]       = __floats2half2_rn(a4[0], a4[1]);
                *(__half2*)&C[(size_t)(r0 + 8) * ldc + cc] = __floats2half2_rn(a4[2], a4[3]);
            } else {
                float* C = (float*)Cp;
                float b0 = 0.f, b1 = 0.f;
                if (BIAS) { float2 bb = *(const float2*)&bias[cc]; b0 = bb.x; b1 = bb.y; }
                *(float2*)&C[(size_t)r0 * ldc + cc]       = make_float2(a4[0] + b0, a4[1] + b1);
                *(float2*)&C[(size_t)(r0 + 8) * ldc + cc] = make_float2(a4[2] + b0, a4[3] + b1);
            }
        }
    }
}

// ---------------------------------------------------------------------------
// k_qkv: qkv[b][m][n] = Wqkv[m,:] . x[b][n,:] with FUSED epilogues:
//  m<1024 (q,k): channel-major store + per-row sum-of-squares partials
//  m>=1024 (v) : transpose in smem, store token-major into g_vt
// ---------------------------------------------------------------------------
__global__ void __launch_bounds__(128, 2) k_qkv()
{
    extern __shared__ char dsm[];
    const int m0 = blockIdx.y * 128;
    const int n0 = blockIdx.x * 128;
    const int b  = blockIdx.z;
    const __half* Bx = g_xh + (size_t)b * Nn * Cn;

    GEMM_MAINLOOP(g_wqh, Bx, 512, 512, 512, m0, n0)

    const int g  = lane >> 2;
    const int tg = lane & 3;

    if (m0 < 1024) {
        __half* C = g_qkv + (size_t)b * 1024 * Nn;
#pragma unroll
        for (int mi = 0; mi < 4; mi++) {
#pragma unroll
            for (int nj = 0; nj < 8; nj++) {
                const int r0 = m0 + wm + mi * 16 + g;
                const int cc = n0 + wn + nj * 8 + 2 * tg;
                float* a4 = acc[mi][nj];
                *(__half2*)&C[(size_t)r0 * Nn + cc]       = __floats2half2_rn(a4[0], a4[1]);
                *(__half2*)&C[(size_t)(r0 + 8) * Nn + cc] = __floats2half2_rn(a4[2], a4[3]);
            }
        }
        float* snorm = (float*)dsm;
        __syncthreads();
        if (tid < 128) snorm[tid] = 0.f;
        __syncthreads();
#pragma unroll
        for (int mi = 0; mi < 4; mi++) {
            float ssA = 0.f, ssB = 0.f;
#pragma unroll
            for (int nj = 0; nj < 8; nj++) {
                float* a4 = acc[mi][nj];
                ssA = fmaf(a4[0], a4[0], fmaf(a4[1], a4[1], ssA));
                ssB = fmaf(a4[2], a4[2], fmaf(a4[3], a4[3], ssB));
            }
            ssA += __shfl_xor_sync(0xffffffffu, ssA, 1);
            ssA += __shfl_xor_sync(0xffffffffu, ssA, 2);
            ssB += __shfl_xor_sync(0xffffffffu, ssB, 1);
            ssB += __shfl_xor_sync(0xffffffffu, ssB, 2);
            if (tg == 0) {
                atomicAdd(&snorm[wm + mi * 16 + g], ssA);
                atomicAdd(&snorm[wm + mi * 16 + g + 8], ssB);
            }
        }
        __syncthreads();
        if (tid < 128)
            g_nP[((size_t)b * 64 + blockIdx.x) * 1024 + m0 + tid] = snorm[tid];
    } else {
        __half* tS = (__half*)dsm;     // [128 n][136 m]
        __syncthreads();
#pragma unroll
        for (int mi = 0; mi < 4; mi++) {
#pragma unroll
            for (int nj = 0; nj < 8; nj++) {
                const int ml = wm + mi * 16 + g;
                const int nl = wn + nj * 8 + 2 * tg;
                float* a4 = acc[mi][nj];
                tS[nl * 136 + ml]           = __float2half_rn(a4[0]);
                tS[(nl + 1) * 136 + ml]     = __float2half_rn(a4[1]);
                tS[nl * 136 + ml + 8]       = __float2half_rn(a4[2]);
                tS[(nl + 1) * 136 + ml + 8] = __float2half_rn(a4[3]);
            }
        }
        __syncthreads();
        const int hd0 = m0 - 1024;
#pragma unroll
        for (int p = 0; p < 4; p++) {
            const int nn = (tid >> 2) + p * 32;
            const int q  = tid & 3;
            const __half* src = tS + nn * 136 + q * 32;
            __half* dst = g_vt + ((size_t)b * Nn + n0 + nn) * Cn + hd0 + q * 32;
#pragma unroll
            for (int k = 0; k < 4; k++)
                ((uint4*)dst)[k] = ((const uint4*)src)[k];
        }
    }
}

// reduce norm partials -> inverse norms
__global__ void __launch_bounds__(256) inv_kernel()
{
    const int idx = blockIdx.x * 256 + threadIdx.x;
    const int b = idx >> 10, m = idx & 1023;
    float s = 0.f;
#pragma unroll 8
    for (int j = 0; j < 64; j++)
        s += g_nP[((size_t)b * 64 + j) * 1024 + m];
    g_inv[b * 1024 + m] = 1.f / fmaxf(sqrtf(s), 1e-12f);
}

// 3. split-K q@k^T partials (fp32 out)
__global__ void __launch_bounds__(128, 2) k_qk()
{
    const int bh = blockIdx.y;
    const __half* qb = g_qkv + ((size_t)(bh >> 2) * 1024 + (bh & 3) * DHn) * Nn
                     + blockIdx.x * 512;
    const __half* kb = qb + (size_t)512 * Nn;
    float* C = g_attnP + ((size_t)bh * QK_SPLIT + blockIdx.x) * (DHn * DHn);
    gemm_big<false, false>(qb, kb, C, nullptr, 512, Nn, Nn, DHn, 0, 0);
}

// 4. reduce + scale + softmax; writes TRANSPOSED attn: g_attnT[bh][d][c]
__global__ void __launch_bounds__(128) softmax_kernel(const float* __restrict__ temp)
{
    const int bh = blockIdx.x >> 7;
    const int c  = blockIdx.x & 127;
    const int b  = bh >> 2, h = bh & 3;
    const int d  = threadIdx.x;

    const float* base = g_attnP + (size_t)bh * QK_SPLIT * (DHn * DHn) + c * DHn + d;
    float s = 0.f;
#pragma unroll
    for (int p = 0; p < QK_SPLIT; p++) s += base[(size_t)p * (DHn * DHn)];

    const float qinv = g_inv[b * 1024 + h * DHn + c];
    const float kinv = g_inv[b * 1024 + 512 + h * DHn + d];
    const float val  = s * qinv * kinv * temp[h];

    __shared__ float red[128];
    red[d] = val;
    __syncthreads();
    for (int off = 64; off; off >>= 1) {
        if (d < off) red[d] = fmaxf(red[d], red[d + off]);
        __syncthreads();
    }
    const float mx = red[0];
    __syncthreads();
    const float e = expf(val - mx);
    red[d] = e;
    __syncthreads();
    for (int off = 64; off; off >>= 1) {
        if (d < off) red[d] += red[d + off];
        __syncthreads();
    }
    g_attnT[(size_t)bh * (DHn * DHn) + d * DHn + c] = __float2half_rn(e / red[0]);
}

// 5. M_b[j][h*128+d] = sum_c Wout[j][h*128+c] * attn_bh[c][d]   (half out)
__global__ void __launch_bounds__(128, 2) k_M()
{
    const int bh = blockIdx.z;
    const int b = bh >> 2, h = bh & 3;
    const __half* A  = g_woh + h * DHn;
    const __half* Bt = g_attnT + (size_t)bh * DHn * DHn;
    __half* C = g_M + (size_t)b * Cn * Cn + h * DHn;
    gemm_big<true, false>(A, Bt, C, nullptr, DHn, 512, DHn, Cn,
                          blockIdx.y * 128, 0);
}

// 6. out[b] = v_t[b] @ M_b^T + bias   (fp32 out)
__global__ void __launch_bounds__(128, 2) k_out(float* __restrict__ out,
                                                const float* __restrict__ bias)
{
    const int b = blockIdx.z;
    const __half* A = g_vt + (size_t)b * Nn * Cn;
    const __half* Bm = g_M + (size_t)b * Cn * Cn;
    float* C = out + (size_t)b * Nn * Cn;
    gemm_big<false, true>(A, Bm, C, bias, 512, 512, 512, 512,
                          blockIdx.y * 128, blockIdx.x * 128);
}

// ---------------- small kernels ---------------------------------------------
__global__ void __launch_bounds__(256) f2h(const float* __restrict__ s,
                                           __half* __restrict__ d, int n4)
{
    const int i = blockIdx.x * 256 + threadIdx.x;
    if (i < n4) {
        float4 v = ((const float4*)s)[i];
        ((__half2*)d)[i * 2]     = __floats2half2_rn(v.x, v.y);
        ((__half2*)d)[i * 2 + 1] = __floats2half2_rn(v.z, v.w);
    }
}

// ---------------------------------------------------------------------------
extern "C" void kernel_launch(void* const* d_in, const int* in_sizes, int n_in,
                              void* d_out, int out_size)
{
    const float* x    = (const float*)d_in[0];
    const float* Wqkv = (const float*)d_in[1];
    const float* Wout = (const float*)d_in[2];
    const float* bout = (const float*)d_in[3];
    const float* temp = (const float*)d_in[4];
    float* out = (float*)d_out;

    __half *xh, *wqh, *woh;
    cudaGetSymbolAddress((void**)&xh,  g_xh);
    cudaGetSymbolAddress((void**)&wqh, g_wqh);
    cudaGetSymbolAddress((void**)&woh, g_woh);

    cudaFuncSetAttribute(k_qkv, cudaFuncAttributeMaxDynamicSharedMemorySize, BIG_SMEM);
    cudaFuncSetAttribute(k_qk,  cudaFuncAttributeMaxDynamicSharedMemorySize, BIG_SMEM);
    cudaFuncSetAttribute(k_M,   cudaFuncAttributeMaxDynamicSharedMemorySize, BIG_SMEM);
    cudaFuncSetAttribute(k_out, cudaFuncAttributeMaxDynamicSharedMemorySize, BIG_SMEM);

    // 0. fp32 -> fp16 conversions
    f2h<<<(Bn * Nn * Cn / 4 + 255) / 256, 256>>>(x, xh, Bn * Nn * Cn / 4);
    f2h<<<(1536 * 512 / 4 + 255) / 256, 256>>>(Wqkv, wqh, 1536 * 512 / 4);
    f2h<<<(512 * 512 / 4 + 255) / 256, 256>>>(Wout, woh, 512 * 512 / 4);

    // 1. QKV GEMM with fused norm partials + v transpose
    k_qkv<<<dim3(64, 12, 4), 128, BIG_SMEM>>>();

    // 2. inverse L2 norms
    inv_kernel<<<16, 256>>>();

    // 3. split-K q@k^T partials
    k_qk<<<dim3(QK_SPLIT, 16), 128, BIG_SMEM>>>();

    // 4. reduce + scale + softmax (transposed output)
    softmax_kernel<<<16 * 128, 128>>>(temp);

    // 5. M = Wout_h @ attn_h  (tiny fused GEMM)
    k_M<<<dim3(1, 4, 16), 128, BIG_SMEM>>>();

    // 6. out = v_t @ M^T + bias
    k_out<<<dim3(4, 64, 4), 128, BIG_SMEM>>>(out, bout);
}